// round 14
// baseline (speedup 1.0000x reference)
#include <cuda_runtime.h>
#include <cuda_bf16.h>
#include <math.h>

#define NN 50000
#define EE 800000
#define HH 128
#define NHH 8
#define DD 16
#define TT 6
#define LL 2

#define APITCH 136                     // bf16 elems per smem row (272 B: conflict-free ldmatrix)
#define ATILE (128 * APITCH * 2)       // bytes per 128x128 bf16 tile with pitch = 34816
#define DSMEM_MMA (3 * ATILE)          // Ahi, Alo, B(single split buffer) = 104448 B -> 2 CTA/SM

typedef unsigned long long u64;
typedef unsigned int u32;

// ---------------- scratch (device globals; no allocation allowed) ----------------
__device__ float g_h[NN * HH];
__device__ float g_kt[NN * HH];
__device__ float g_q[NN * HH];
__device__ float g_vm[NN * HH];
__device__ float g_trans[NN * HH];
__device__ float g_hid[NN * HH];
__device__ float g_cn[NN * HH];
// bf16 split weights per (l,t,mat 0..3): [split2][n128][k128] = 32768 bf16 (65536 B)
__device__ __align__(16) __nv_bfloat16 g_wb[(size_t)LL * TT * 4 * 32768];
__device__ int g_tcnt[TT];
__device__ int g_toff[TT + 1];
__device__ int g_tcur[TT];
__device__ int g_tnodes[NN];
__device__ int g_dcnt[NN];
__device__ int g_doff[NN + 1];
__device__ int g_dcur[NN];
__device__ int g_csrc[EE];
__device__ int g_bsum[64];

// ---------------- helpers ----------------
__device__ __forceinline__ float geluf(float x) {
    float x3 = x * x * x;
    return 0.5f * x * (1.0f + tanhf(0.7978845608028654f * (x + 0.044715f * x3)));
}
__device__ __forceinline__ u32 smem_u32(const void* p) {
    u32 a;
    asm("{ .reg .u64 t; cvta.to.shared.u64 t, %1; cvt.u32.u64 %0, t; }" : "=r"(a) : "l"(p));
    return a;
}
__device__ __forceinline__ void ldsm4(u32* r, u32 addr) {
    asm volatile("ldmatrix.sync.aligned.m8n8.x4.shared.b16 {%0,%1,%2,%3}, [%4];"
                 : "=r"(r[0]), "=r"(r[1]), "=r"(r[2]), "=r"(r[3]) : "r"(addr));
}
__device__ __forceinline__ void mma16816(float* c, const u32* a, u32 b0, u32 b1) {
    asm volatile(
        "mma.sync.aligned.m16n8k16.row.col.f32.bf16.bf16.f32 "
        "{%0,%1,%2,%3}, {%4,%5,%6,%7}, {%8,%9}, {%0,%1,%2,%3};"
        : "+f"(c[0]), "+f"(c[1]), "+f"(c[2]), "+f"(c[3])
        : "r"(a[0]), "r"(a[1]), "r"(a[2]), "r"(a[3]), "r"(b0), "r"(b1));
}
// split fp32x4 -> packed bf16 hi/lo u64s
__device__ __forceinline__ void split4(float4 hv, u64& hp, u64& lp) {
    __nv_bfloat16 h0 = __float2bfloat16(hv.x), h1 = __float2bfloat16(hv.y),
                  h2 = __float2bfloat16(hv.z), h3 = __float2bfloat16(hv.w);
    __nv_bfloat16 l0 = __float2bfloat16(hv.x - __bfloat162float(h0));
    __nv_bfloat16 l1 = __float2bfloat16(hv.y - __bfloat162float(h1));
    __nv_bfloat16 l2 = __float2bfloat16(hv.z - __bfloat162float(h2));
    __nv_bfloat16 l3 = __float2bfloat16(hv.w - __bfloat162float(h3));
    hp = ((u64)((((u32)__bfloat16_as_ushort(h3)) << 16) | __bfloat16_as_ushort(h2)) << 32)
         | ((((u32)__bfloat16_as_ushort(h1)) << 16) | __bfloat16_as_ushort(h0));
    lp = ((u64)((((u32)__bfloat16_as_ushort(l3)) << 16) | __bfloat16_as_ushort(l2)) << 32)
         | ((((u32)__bfloat16_as_ushort(l1)) << 16) | __bfloat16_as_ushort(l0));
}

// ---------------- setup kernels ----------------
// k_zero is gone: k_combine zeroes dcnt/dcur/tcnt/tcur for the NEXT call
// (device globals are statically zero-initialized, so call 1 is also correct).

__global__ void k_count(const int* __restrict__ edst, const int* __restrict__ nt) {
    __shared__ int sh[TT];
    int tid = threadIdx.x;
    if (tid < TT) sh[tid] = 0;
    __syncthreads();
    int i = blockIdx.x * blockDim.x + tid;
    int stride = gridDim.x * blockDim.x;
    for (int e = i; e < EE; e += stride) atomicAdd(&g_dcnt[edst[e]], 1);
    for (int n = i; n < NN; n += stride) atomicAdd(&sh[nt[n]], 1);
    __syncthreads();
    if (tid < TT) atomicAdd(&g_tcnt[tid], sh[tid]);
}

__global__ void k_scanA() {
    __shared__ int wsum[32];
    int b = blockIdx.x, tid = threadIdx.x, lane = tid & 31, wid = tid >> 5;
    int i = b * 1024 + tid;
    int v = (i < NN) ? g_dcnt[i] : 0;
    int x = v;
    #pragma unroll
    for (int o = 1; o < 32; o <<= 1) {
        int y = __shfl_up_sync(0xffffffffu, x, o);
        if (lane >= o) x += y;
    }
    if (lane == 31) wsum[wid] = x;
    __syncthreads();
    if (wid == 0) {
        int w = wsum[lane];
        #pragma unroll
        for (int o = 1; o < 32; o <<= 1) {
            int y = __shfl_up_sync(0xffffffffu, w, o);
            if (lane >= o) w += y;
        }
        wsum[lane] = w;
    }
    __syncthreads();
    int incl = x + (wid > 0 ? wsum[wid - 1] : 0);
    if (i < NN) g_doff[i] = incl - v;
    if (tid == 1023) g_bsum[b] = incl;
}

// scanC: per-block redundant 64-wide scan of chunk totals; adds base; block 0
// also writes doff[NN] and the type offsets.
__global__ void k_scanC(int nchunks) {
    __shared__ int schunk[64];
    __shared__ int wtot[2];
    int tid = threadIdx.x;
    int lane = tid & 31;
    if (tid < 64) {
        int v = (tid < nchunks) ? g_bsum[tid] : 0;
        int x = v;
        #pragma unroll
        for (int o = 1; o < 32; o <<= 1) {
            int y = __shfl_up_sync(0xffffffffu, x, o);
            if (lane >= o) x += y;
        }
        if (lane == 31) wtot[tid >> 5] = x;
        schunk[tid] = x - v;   // exclusive within warp
    }
    __syncthreads();
    if (tid >= 32 && tid < 64) schunk[tid] += wtot[0];
    __syncthreads();
    int i = blockIdx.x * blockDim.x + tid;
    if (i < NN) g_doff[i] += schunk[i >> 10];
    if (blockIdx.x == 0 && tid == 0) {
        g_doff[NN] = wtot[0] + wtot[1];
        int r = 0;
        for (int t = 0; t < TT; t++) { g_toff[t] = r; r += g_tcnt[t]; }
        g_toff[TT] = r;
    }
}

__global__ void k_scatter(const int* __restrict__ nt, const int* __restrict__ esrc,
                          const int* __restrict__ edst) {
    int i = blockIdx.x * blockDim.x + threadIdx.x;
    int stride = gridDim.x * blockDim.x;
    for (int n = i; n < NN; n += stride) {
        int t = nt[n];
        int p = atomicAdd(&g_tcur[t], 1);
        g_tnodes[g_toff[t] + p] = n;
    }
    for (int e = i; e < EE; e += stride) {
        int d = edst[e];
        int p = atomicAdd(&g_dcur[d], 1);
        g_csrc[g_doff[d] + p] = esrc[e];
    }
}

// ---------------- weight prep + next-call counter reset ----------------
// mat 0: Wk*rel_att*(rel_pri/4), mat 1: Wq, mat 2: Wv*rel_msg, mat 3: Wa.
__global__ void k_combine(const float* __restrict__ Wk, const float* __restrict__ Wq,
                          const float* __restrict__ Wv, const float* __restrict__ Wa,
                          const float* __restrict__ rel_att, const float* __restrict__ rel_msg,
                          const float* __restrict__ rel_pri) {
    int t = blockIdx.x, mat = blockIdx.y, l = blockIdx.z;
    __shared__ float sA[NHH * DD * DD];
    __shared__ float sScl[NHH];
    const float* W = (mat == 0 ? Wk : (mat == 1 ? Wq : (mat == 2 ? Wv : Wa)))
                     + (size_t)(l * TT + t) * HH * HH;
    const float* A = (mat == 0 ? rel_att : rel_msg) + (size_t)l * NHH * DD * DD;
    __nv_bfloat16* out = g_wb + (((size_t)l * TT + t) * 4 + mat) * 32768;
    bool fold = (mat == 0 || mat == 2);
    if (fold) {
        for (int idx = threadIdx.x; idx < NHH * DD * DD; idx += blockDim.x) sA[idx] = A[idx];
        if (threadIdx.x < NHH)
            sScl[threadIdx.x] = (mat == 0) ? rel_pri[l * NHH + threadIdx.x] * 0.25f : 1.0f;
    }
    __syncthreads();
    for (int idx = threadIdx.x; idx < HH * HH; idx += blockDim.x) {
        int i = idx >> 7, c = idx & 127;
        float v;
        if (!fold) {
            v = W[i * HH + c];
        } else {
            int h = c >> 4, f = c & 15;
            float s = 0.0f;
            #pragma unroll
            for (int d = 0; d < DD; d++)
                s += W[i * HH + h * DD + d] * sA[h * DD * DD + d * DD + f];
            v = s * sScl[h];
        }
        __nv_bfloat16 hi = __float2bfloat16(v);
        __nv_bfloat16 lo = __float2bfloat16(v - __bfloat162float(hi));
        out[c * 128 + i] = hi;
        out[16384 + c * 128 + i] = lo;
    }
    // Counter reset for the next call (this kernel runs after all consumers).
    int gid = ((blockIdx.z * 4 + blockIdx.y) * TT + blockIdx.x) * blockDim.x + threadIdx.x;
    int gstr = TT * 4 * LL * blockDim.x;   // 12288
    for (int j = gid; j < NN; j += gstr) { g_dcnt[j] = 0; g_dcur[j] = 0; }
    if (gid < TT) { g_tcnt[gid] = 0; g_tcur[gid] = 0; }
}

// ---------------- mma.sync projection kernel (fp32 outputs restored) ----------------
__global__ void __launch_bounds__(256, 2)
k_proj_mma(const float* __restrict__ ext_hidden, const float* __restrict__ xn,
           const float* __restrict__ Wpos, int l) {
    int t = blockIdx.y;
    int beg = g_toff[t], end = g_toff[t + 1];
    int base = beg + (int)blockIdx.x * 128;
    if (base >= end) return;
    int cnt = min(128, end - base);

    extern __shared__ __align__(16) char dyns[];
    __shared__ int nidx[128];
    __shared__ float sxn0[128], sxn1[128];

    int tid = threadIdx.x;
    int wid = tid >> 5, lane = tid & 31;

    u32 sbase = smem_u32(dyns);
    u32 Ahi = sbase, Alo = sbase + ATILE, Bb = sbase + 2 * ATILE;

    if (tid < 128) {
        int slot = (tid < cnt) ? tid : 0;
        int n = g_tnodes[base + slot];
        nidx[tid] = n;
        sxn0[tid] = (tid < cnt) ? xn[2 * n] : 0.f;
        sxn1[tid] = (tid < cnt) ? xn[2 * n + 1] : 0.f;
    }
    __syncthreads();

    const float* hin = (l == 0) ? ext_hidden : g_hid;
    float4 wpA = ((const float4*)(Wpos + l * 2 * HH))[lane];
    float4 wpB = ((const float4*)(Wpos + l * 2 * HH + HH))[lane];
    #pragma unroll 4
    for (int r = wid; r < 128; r += 8) {
        float4 hv = make_float4(0.f, 0.f, 0.f, 0.f);
        if (r < cnt) {
            size_t rowoff = (size_t)nidx[r] * HH;
            hv = *((const float4*)(hin + rowoff) + lane);
            float x0 = sxn0[r], x1 = sxn1[r];
            hv.x += x0 * wpA.x + x1 * wpB.x;
            hv.y += x0 * wpA.y + x1 * wpB.y;
            hv.z += x0 * wpA.z + x1 * wpB.z;
            hv.w += x0 * wpA.w + x1 * wpB.w;
            *((float4*)(g_h + rowoff) + lane) = hv;
        }
        u64 hp, lp;
        split4(hv, hp, lp);
        u32 off = (u32)r * (APITCH * 2) + (u32)lane * 8;
        *(u64*)(dyns + off) = hp;
        *(u64*)(dyns + ATILE + off) = lp;
    }

    const u64* wb64 = (const u64*)g_wb;
    int m0 = wid * 16;
    u32 aro = (u32)((m0 + (lane & 15)) * APITCH + (lane >> 4) * 8) * 2;
    // ldsm4-B lane map: g2 = lane>>4 selects nt-pair member; khalf = (lane>>3)&1; row = lane&7
    u32 bro4 = (u32)((((lane >> 4) * 8 + (lane & 7)) * APITCH) + ((lane >> 3) & 1) * 8) * 2;
    int r0 = m0 + (lane >> 2), r1 = r0 + 8;

    for (int mat = 0; mat < 3; mat++) {
        float c[16][4];
        #pragma unroll
        for (int nt = 0; nt < 16; nt++) {
            c[nt][0] = 0.f; c[nt][1] = 0.f; c[nt][2] = 0.f; c[nt][3] = 0.f;
        }
        size_t wbase = (((size_t)l * TT + t) * 4 + mat) * 8192;
        #pragma unroll
        for (int s = 0; s < 2; s++) {
            __syncthreads();
            #pragma unroll 4
            for (int j = tid; j < 4096; j += 256) {
                u64 v = wb64[wbase + s * 4096 + j];
                int n = j >> 5, k4 = j & 31;
                *(u64*)(dyns + 2 * ATILE + n * (APITCH * 2) + k4 * 8) = v;
            }
            __syncthreads();
            #pragma unroll
            for (int ks = 0; ks < 8; ks++) {
                u32 a0[4], a1[4];
                ldsm4(a0, Ahi + aro + ks * 32);
                if (s == 0) ldsm4(a1, Alo + aro + ks * 32);
                #pragma unroll
                for (int nt = 0; nt < 16; nt += 2) {
                    u32 b[4];
                    ldsm4(b, Bb + bro4 + (u32)nt * 8 * (APITCH * 2) + ks * 32);
                    mma16816(c[nt], a0, b[0], b[1]);
                    mma16816(c[nt + 1], a0, b[2], b[3]);
                    if (s == 0) {
                        mma16816(c[nt], a1, b[0], b[1]);
                        mma16816(c[nt + 1], a1, b[2], b[3]);
                    }
                }
            }
        }
        float* dst = (mat == 0) ? g_kt : (mat == 1) ? g_q : g_vm;
        #pragma unroll
        for (int nt = 0; nt < 16; nt++) {
            int col = nt * 8 + (lane & 3) * 2;
            if (r0 < cnt)
                *(float2*)(dst + (size_t)nidx[r0] * HH + col) = make_float2(c[nt][0], c[nt][1]);
            if (r1 < cnt)
                *(float2*)(dst + (size_t)nidx[r1] * HH + col) = make_float2(c[nt][2], c[nt][3]);
        }
    }
}

// ---------------- edge kernel: fp32 gathers, 4-wide unroll (MLP 8) ----------------
__global__ void k_edge() {
    int warp = threadIdx.x >> 5, lane = threadIdx.x & 31;
    int n = blockIdx.x * 8 + warp;
    if (n >= NN) return;
    int beg = g_doff[n], end = g_doff[n + 1];
    float* outp = g_trans + (size_t)n * HH + lane * 4;
    if (beg == end) {
        *(float4*)outp = make_float4(0.f, 0.f, 0.f, 0.f);
        return;
    }
    float4 q4 = *(const float4*)(g_q + (size_t)n * HH + lane * 4);

    int src0 = g_csrc[beg];
    float4 k0 = *(const float4*)(g_kt + (size_t)src0 * HH + lane * 4);
    float4 v0 = *(const float4*)(g_vm + (size_t)src0 * HH + lane * 4);
    float C = k0.x * q4.x + k0.y * q4.y + k0.z * q4.z + k0.w * q4.w;
    C += __shfl_xor_sync(0xffffffffu, C, 1);
    C += __shfl_xor_sync(0xffffffffu, C, 2);

    float den0 = 1.0f, den1 = 0.f, den2 = 0.f, den3 = 0.f;
    float ax0 = v0.x, ay0 = v0.y, az0 = v0.z, aw0 = v0.w;
    float ax1 = 0.f, ay1 = 0.f, az1 = 0.f, aw1 = 0.f;
    float ax2 = 0.f, ay2 = 0.f, az2 = 0.f, aw2 = 0.f;
    float ax3 = 0.f, ay3 = 0.f, az3 = 0.f, aw3 = 0.f;

    for (int b = beg + 1; b < end; b += 32) {
        int nchunk = min(32, end - b);
        int srcs = (b + lane < end) ? g_csrc[b + lane] : 0;
        int j = 0;
        for (; j + 4 <= nchunk; j += 4) {
            int sA = __shfl_sync(0xffffffffu, srcs, j);
            int sB = __shfl_sync(0xffffffffu, srcs, j + 1);
            int sC = __shfl_sync(0xffffffffu, srcs, j + 2);
            int sD = __shfl_sync(0xffffffffu, srcs, j + 3);
            float4 kA = *(const float4*)(g_kt + (size_t)sA * HH + lane * 4);
            float4 kB = *(const float4*)(g_kt + (size_t)sB * HH + lane * 4);
            float4 kC = *(const float4*)(g_kt + (size_t)sC * HH + lane * 4);
            float4 kD = *(const float4*)(g_kt + (size_t)sD * HH + lane * 4);
            float4 vA = *(const float4*)(g_vm + (size_t)sA * HH + lane * 4);
            float4 vB = *(const float4*)(g_vm + (size_t)sB * HH + lane * 4);
            float4 vC = *(const float4*)(g_vm + (size_t)sC * HH + lane * 4);
            float4 vD = *(const float4*)(g_vm + (size_t)sD * HH + lane * 4);
            float sa = kA.x * q4.x + kA.y * q4.y + kA.z * q4.z + kA.w * q4.w;
            float sb = kB.x * q4.x + kB.y * q4.y + kB.z * q4.z + kB.w * q4.w;
            float sc = kC.x * q4.x + kC.y * q4.y + kC.z * q4.z + kC.w * q4.w;
            float sd = kD.x * q4.x + kD.y * q4.y + kD.z * q4.z + kD.w * q4.w;
            sa += __shfl_xor_sync(0xffffffffu, sa, 1);
            sb += __shfl_xor_sync(0xffffffffu, sb, 1);
            sc += __shfl_xor_sync(0xffffffffu, sc, 1);
            sd += __shfl_xor_sync(0xffffffffu, sd, 1);
            sa += __shfl_xor_sync(0xffffffffu, sa, 2);
            sb += __shfl_xor_sync(0xffffffffu, sb, 2);
            sc += __shfl_xor_sync(0xffffffffu, sc, 2);
            sd += __shfl_xor_sync(0xffffffffu, sd, 2);
            float pa = __expf(sa - C);
            float pb = __expf(sb - C);
            float pc = __expf(sc - C);
            float pd = __expf(sd - C);
            den0 += pa; den1 += pb; den2 += pc; den3 += pd;
            ax0 += pa * vA.x; ax1 += pb * vB.x; ax2 += pc * vC.x; ax3 += pd * vD.x;
            ay0 += pa * vA.y; ay1 += pb * vB.y; ay2 += pc * vC.y; ay3 += pd * vD.y;
            az0 += pa * vA.z; az1 += pb * vB.z; az2 += pc * vC.z; az3 += pd * vD.z;
            aw0 += pa * vA.w; aw1 += pb * vB.w; aw2 += pc * vC.w; aw3 += pd * vD.w;
        }
        for (; j < nchunk; j++) {
            int sA = __shfl_sync(0xffffffffu, srcs, j);
            float4 kA = *(const float4*)(g_kt + (size_t)sA * HH + lane * 4);
            float4 vA = *(const float4*)(g_vm + (size_t)sA * HH + lane * 4);
            float sa = kA.x * q4.x + kA.y * q4.y + kA.z * q4.z + kA.w * q4.w;
            sa += __shfl_xor_sync(0xffffffffu, sa, 1);
            sa += __shfl_xor_sync(0xffffffffu, sa, 2);
            float pa = __expf(sa - C);
            den0 += pa;
            ax0 += pa * vA.x; ay0 += pa * vA.y;
            az0 += pa * vA.z; aw0 += pa * vA.w;
        }
    }
    float inv = 1.0f / (den0 + den1 + den2 + den3 + 1e-16f);
    float4 o;
    o.x = geluf((ax0 + ax1 + ax2 + ax3) * inv);
    o.y = geluf((ay0 + ay1 + ay2 + ay3) * inv);
    o.z = geluf((az0 + az1 + az2 + az3) * inv);
    o.w = geluf((aw0 + aw1 + aw2 + aw3) * inv);
    *(float4*)outp = o;
}

// ---------------- mma.sync output kernel: out = trans @ Wa[t] + fused epilogue ----------------
__global__ void __launch_bounds__(256, 2)
k_out_mma(const float* __restrict__ skip,
          const float* __restrict__ ext_cn, const float* __restrict__ ext_hidden,
          const float* __restrict__ w_pri,
          float* __restrict__ out_cn, float* __restrict__ out_hid,
          float* __restrict__ out_pri, int l) {
    int t = blockIdx.y;
    int beg = g_toff[t], end = g_toff[t + 1];
    int base = beg + (int)blockIdx.x * 128;
    if (base >= end) return;
    int cnt = min(128, end - base);

    extern __shared__ __align__(16) char dyns[];
    __shared__ int nidx[128];
    __shared__ float ssk;
    __shared__ float swpri[128];

    int tid = threadIdx.x;
    int wid = tid >> 5, lane = tid & 31;

    u32 sbase = smem_u32(dyns);
    u32 Ahi = sbase, Alo = sbase + ATILE, Bb = sbase + 2 * ATILE;

    if (tid < 128) {
        nidx[tid] = g_tnodes[base + ((tid < cnt) ? tid : 0)];
        swpri[tid] = (l == LL - 1) ? w_pri[l * HH + tid] : 0.f;
    }
    if (tid == 0) ssk = 1.0f / (1.0f + __expf(-skip[l * TT + t]));
    __syncthreads();

    #pragma unroll 4
    for (int r = wid; r < 128; r += 8) {
        float4 hv = make_float4(0.f, 0.f, 0.f, 0.f);
        if (r < cnt)
            hv = *((const float4*)(g_trans + (size_t)nidx[r] * HH) + lane);
        u64 hp, lp;
        split4(hv, hp, lp);
        u32 off = (u32)r * (APITCH * 2) + (u32)lane * 8;
        *(u64*)(dyns + off) = hp;
        *(u64*)(dyns + ATILE + off) = lp;
    }

    const u64* wb64 = (const u64*)g_wb;
    int m0 = wid * 16;
    u32 aro = (u32)((m0 + (lane & 15)) * APITCH + (lane >> 4) * 8) * 2;
    u32 bro4 = (u32)((((lane >> 4) * 8 + (lane & 7)) * APITCH) + ((lane >> 3) & 1) * 8) * 2;
    int r0 = m0 + (lane >> 2), r1 = r0 + 8;

    float c[16][4];
    #pragma unroll
    for (int nt = 0; nt < 16; nt++) {
        c[nt][0] = 0.f; c[nt][1] = 0.f; c[nt][2] = 0.f; c[nt][3] = 0.f;
    }
    size_t wbase = (((size_t)l * TT + t) * 4 + 3) * 8192;   // mat 3 = Wa
    #pragma unroll
    for (int s = 0; s < 2; s++) {
        __syncthreads();
        #pragma unroll 4
        for (int j = tid; j < 4096; j += 256) {
            u64 v = wb64[wbase + s * 4096 + j];
            int n = j >> 5, k4 = j & 31;
            *(u64*)(dyns + 2 * ATILE + n * (APITCH * 2) + k4 * 8) = v;
        }
        __syncthreads();
        #pragma unroll
        for (int ks = 0; ks < 8; ks++) {
            u32 a0[4], a1[4];
            ldsm4(a0, Ahi + aro + ks * 32);
            if (s == 0) ldsm4(a1, Alo + aro + ks * 32);
            #pragma unroll
            for (int nt = 0; nt < 16; nt += 2) {
                u32 b[4];
                ldsm4(b, Bb + bro4 + (u32)nt * 8 * (APITCH * 2) + ks * 32);
                mma16816(c[nt], a0, b[0], b[1]);
                mma16816(c[nt + 1], a0, b[2], b[3]);
                if (s == 0) {
                    mma16816(c[nt], a1, b[0], b[1]);
                    mma16816(c[nt + 1], a1, b[2], b[3]);
                }
            }
        }
    }

    const float* cn_in = (l == 0) ? ext_cn : g_cn;
    const float* hid_in = (l == 0) ? ext_hidden : g_hid;
    float* cn_o = (l == LL - 1) ? out_cn : g_cn;
    float* hid_o = (l == LL - 1) ? out_hid : g_hid;
    float sk = ssk, omsk = 1.0f - ssk;
    float pri0 = 0.f, pri1 = 0.f;
    size_t off0 = (size_t)nidx[r0 < cnt ? r0 : 0] * HH;
    size_t off1 = (size_t)nidx[r1 < cnt ? r1 : 0] * HH;
    #pragma unroll
    for (int nt = 0; nt < 16; nt++) {
        int col = nt * 8 + (lane & 3) * 2;
        if (r0 < cnt) {
            float2 hh = *(const float2*)(g_h + off0 + col);
            float2 cc = *(const float2*)(cn_in + off0 + col);
            float2 dd = *(const float2*)(hid_in + off0 + col);
            float hgx = sk * c[nt][0] + omsk * hh.x;
            float hgy = sk * c[nt][1] + omsk * hh.y;
            float cnx = hgx + cc.x, cny = hgy + cc.y;
            *(float2*)(cn_o + off0 + col) = make_float2(cnx, cny);
            *(float2*)(hid_o + off0 + col) = make_float2(dd.x + tanhf(cnx), dd.y + tanhf(cny));
            pri0 += hgx * swpri[col] + hgy * swpri[col + 1];
        }
        if (r1 < cnt) {
            float2 hh = *(const float2*)(g_h + off1 + col);
            float2 cc = *(const float2*)(cn_in + off1 + col);
            float2 dd = *(const float2*)(hid_in + off1 + col);
            float hgx = sk * c[nt][2] + omsk * hh.x;
            float hgy = sk * c[nt][3] + omsk * hh.y;
            float cnx = hgx + cc.x, cny = hgy + cc.y;
            *(float2*)(cn_o + off1 + col) = make_float2(cnx, cny);
            *(float2*)(hid_o + off1 + col) = make_float2(dd.x + tanhf(cnx), dd.y + tanhf(cny));
            pri1 += hgx * swpri[col] + hgy * swpri[col + 1];
        }
    }
    if (l == LL - 1) {
        pri0 += __shfl_xor_sync(0xffffffffu, pri0, 1);
        pri0 += __shfl_xor_sync(0xffffffffu, pri0, 2);
        pri1 += __shfl_xor_sync(0xffffffffu, pri1, 1);
        pri1 += __shfl_xor_sync(0xffffffffu, pri1, 2);
        if ((lane & 3) == 0) {
            if (r0 < cnt) out_pri[nidx[r0]] = 1.0f / (1.0f + __expf(-pri0));
            if (r1 < cnt) out_pri[nidx[r1]] = 1.0f / (1.0f + __expf(-pri1));
        }
    }
}

// ---------------- launch ----------------
extern "C" void kernel_launch(void* const* d_in, const int* in_sizes, int n_in,
                              void* d_out, int out_size) {
    const float* in_hidden = (const float*)d_in[0];
    const float* in_cn     = (const float*)d_in[1];
    const float* in_x      = (const float*)d_in[2];
    const int*   node_type = (const int*)d_in[3];
    const int*   edge_src  = (const int*)d_in[4];
    const int*   edge_dst  = (const int*)d_in[5];
    const float* W_pos     = (const float*)d_in[6];
    const float* Wk        = (const float*)d_in[7];
    const float* Wq        = (const float*)d_in[8];
    const float* Wv        = (const float*)d_in[9];
    const float* Wa        = (const float*)d_in[10];
    const float* rel_att   = (const float*)d_in[11];
    const float* rel_msg   = (const float*)d_in[12];
    const float* rel_pri   = (const float*)d_in[13];
    const float* skip      = (const float*)d_in[14];
    const float* w_pri     = (const float*)d_in[15];

    float* out = (float*)d_out;
    float* out_hid = out;
    float* out_cn = out + (size_t)NN * HH;
    float* out_pri = out + (size_t)2 * NN * HH;

    cudaFuncSetAttribute(k_proj_mma, cudaFuncAttributeMaxDynamicSharedMemorySize, DSMEM_MMA);
    cudaFuncSetAttribute(k_out_mma, cudaFuncAttributeMaxDynamicSharedMemorySize, DSMEM_MMA);

    int nchunks = (NN + 1023) / 1024;  // 49

    k_count<<<784, 256>>>(edge_dst, node_type);
    k_scanA<<<nchunks, 1024>>>();
    k_scanC<<<196, 256>>>(nchunks);
    k_scatter<<<784, 256>>>(node_type, edge_src, edge_dst);
    k_combine<<<dim3(TT, 4, LL), 256>>>(Wk, Wq, Wv, Wa, rel_att, rel_msg, rel_pri);

    int tiles128 = (NN + 127) / 128;
    int nodeblk = (NN + 7) / 8;

    for (int l = 0; l < LL; l++) {
        k_proj_mma<<<dim3(tiles128, TT), 256, DSMEM_MMA>>>(in_hidden, in_x, W_pos, l);
        k_edge<<<nodeblk, 256>>>();
        k_out_mma<<<dim3(tiles128, TT), 256, DSMEM_MMA>>>(skip, in_cn, in_hidden, w_pri,
                                                          out_cn, out_hid, out_pri, l);
    }
}

// round 15
// speedup vs baseline: 1.0626x; 1.0626x over previous
#include <cuda_runtime.h>
#include <cuda_bf16.h>
#include <math.h>

#define NN 50000
#define EE 800000
#define HH 128
#define NHH 8
#define DD 16
#define TT 6
#define LL 2

#define APITCH 136                     // bf16 elems per smem row (272 B: conflict-free ldmatrix)
#define ATILE (128 * APITCH * 2)       // bytes per 128x128 bf16 tile with pitch = 34816
#define DSMEM_MMA (3 * ATILE)          // Ahi, Alo, B(single split buffer) = 104448 B -> 2 CTA/SM

typedef unsigned long long u64;
typedef unsigned int u32;

// ---------------- scratch (device globals; no allocation allowed) ----------------
__device__ float g_h[NN * HH];
__device__ float g_kt[NN * HH];
__device__ float g_q[NN * HH];
__device__ float g_vm[NN * HH];
__device__ float g_trans[NN * HH];
__device__ float g_hid[NN * HH];
__device__ float g_cn[NN * HH];
// bf16 split weights per (l,t,mat 0..3): [split2][n128][k128] = 32768 bf16 (65536 B)
__device__ __align__(16) __nv_bfloat16 g_wb[(size_t)LL * TT * 4 * 32768];
__device__ int g_tcnt[TT];
__device__ int g_toff[TT + 1];
__device__ int g_tcur[TT];
__device__ int g_tnodes[NN];
__device__ int g_dcnt[NN];
__device__ int g_doff[NN + 1];
__device__ int g_dcur[NN];
__device__ int g_csrc[EE];
__device__ int g_bsum[64];

// ---------------- helpers ----------------
__device__ __forceinline__ float geluf(float x) {
    float x3 = x * x * x;
    return 0.5f * x * (1.0f + tanhf(0.7978845608028654f * (x + 0.044715f * x3)));
}
__device__ __forceinline__ u32 smem_u32(const void* p) {
    u32 a;
    asm("{ .reg .u64 t; cvta.to.shared.u64 t, %1; cvt.u32.u64 %0, t; }" : "=r"(a) : "l"(p));
    return a;
}
__device__ __forceinline__ void ldsm4(u32* r, u32 addr) {
    asm volatile("ldmatrix.sync.aligned.m8n8.x4.shared.b16 {%0,%1,%2,%3}, [%4];"
                 : "=r"(r[0]), "=r"(r[1]), "=r"(r[2]), "=r"(r[3]) : "r"(addr));
}
__device__ __forceinline__ void mma16816(float* c, const u32* a, u32 b0, u32 b1) {
    asm volatile(
        "mma.sync.aligned.m16n8k16.row.col.f32.bf16.bf16.f32 "
        "{%0,%1,%2,%3}, {%4,%5,%6,%7}, {%8,%9}, {%0,%1,%2,%3};"
        : "+f"(c[0]), "+f"(c[1]), "+f"(c[2]), "+f"(c[3])
        : "r"(a[0]), "r"(a[1]), "r"(a[2]), "r"(a[3]), "r"(b0), "r"(b1));
}
// split fp32x4 -> packed bf16 hi/lo u64s
__device__ __forceinline__ void split4(float4 hv, u64& hp, u64& lp) {
    __nv_bfloat16 h0 = __float2bfloat16(hv.x), h1 = __float2bfloat16(hv.y),
                  h2 = __float2bfloat16(hv.z), h3 = __float2bfloat16(hv.w);
    __nv_bfloat16 l0 = __float2bfloat16(hv.x - __bfloat162float(h0));
    __nv_bfloat16 l1 = __float2bfloat16(hv.y - __bfloat162float(h1));
    __nv_bfloat16 l2 = __float2bfloat16(hv.z - __bfloat162float(h2));
    __nv_bfloat16 l3 = __float2bfloat16(hv.w - __bfloat162float(h3));
    hp = ((u64)((((u32)__bfloat16_as_ushort(h3)) << 16) | __bfloat16_as_ushort(h2)) << 32)
         | ((((u32)__bfloat16_as_ushort(h1)) << 16) | __bfloat16_as_ushort(h0));
    lp = ((u64)((((u32)__bfloat16_as_ushort(l3)) << 16) | __bfloat16_as_ushort(l2)) << 32)
         | ((((u32)__bfloat16_as_ushort(l1)) << 16) | __bfloat16_as_ushort(l0));
}

// ---------------- setup kernels ----------------
// k_zero is gone: k_combine zeroes dcnt/dcur/tcnt/tcur for the NEXT call
// (device globals are statically zero-initialized, so call 1 is also correct).

__global__ void k_count(const int* __restrict__ edst, const int* __restrict__ nt) {
    __shared__ int sh[TT];
    int tid = threadIdx.x;
    if (tid < TT) sh[tid] = 0;
    __syncthreads();
    int i = blockIdx.x * blockDim.x + tid;
    int stride = gridDim.x * blockDim.x;
    for (int e = i; e < EE; e += stride) atomicAdd(&g_dcnt[edst[e]], 1);
    for (int n = i; n < NN; n += stride) atomicAdd(&sh[nt[n]], 1);
    __syncthreads();
    if (tid < TT) atomicAdd(&g_tcnt[tid], sh[tid]);
}

__global__ void k_scanA() {
    __shared__ int wsum[32];
    int b = blockIdx.x, tid = threadIdx.x, lane = tid & 31, wid = tid >> 5;
    int i = b * 1024 + tid;
    int v = (i < NN) ? g_dcnt[i] : 0;
    int x = v;
    #pragma unroll
    for (int o = 1; o < 32; o <<= 1) {
        int y = __shfl_up_sync(0xffffffffu, x, o);
        if (lane >= o) x += y;
    }
    if (lane == 31) wsum[wid] = x;
    __syncthreads();
    if (wid == 0) {
        int w = wsum[lane];
        #pragma unroll
        for (int o = 1; o < 32; o <<= 1) {
            int y = __shfl_up_sync(0xffffffffu, w, o);
            if (lane >= o) w += y;
        }
        wsum[lane] = w;
    }
    __syncthreads();
    int incl = x + (wid > 0 ? wsum[wid - 1] : 0);
    if (i < NN) g_doff[i] = incl - v;
    if (tid == 1023) g_bsum[b] = incl;
}

// scanC: per-block redundant 64-wide scan of chunk totals; adds base; block 0
// also writes doff[NN] and the type offsets.
__global__ void k_scanC(int nchunks) {
    __shared__ int schunk[64];
    __shared__ int wtot[2];
    int tid = threadIdx.x;
    int lane = tid & 31;
    if (tid < 64) {
        int v = (tid < nchunks) ? g_bsum[tid] : 0;
        int x = v;
        #pragma unroll
        for (int o = 1; o < 32; o <<= 1) {
            int y = __shfl_up_sync(0xffffffffu, x, o);
            if (lane >= o) x += y;
        }
        if (lane == 31) wtot[tid >> 5] = x;
        schunk[tid] = x - v;   // exclusive within warp
    }
    __syncthreads();
    if (tid >= 32 && tid < 64) schunk[tid] += wtot[0];
    __syncthreads();
    int i = blockIdx.x * blockDim.x + tid;
    if (i < NN) g_doff[i] += schunk[i >> 10];
    if (blockIdx.x == 0 && tid == 0) {
        g_doff[NN] = wtot[0] + wtot[1];
        int r = 0;
        for (int t = 0; t < TT; t++) { g_toff[t] = r; r += g_tcnt[t]; }
        g_toff[TT] = r;
    }
}

__global__ void k_scatter(const int* __restrict__ nt, const int* __restrict__ esrc,
                          const int* __restrict__ edst) {
    int i = blockIdx.x * blockDim.x + threadIdx.x;
    int stride = gridDim.x * blockDim.x;
    for (int n = i; n < NN; n += stride) {
        int t = nt[n];
        int p = atomicAdd(&g_tcur[t], 1);
        g_tnodes[g_toff[t] + p] = n;
    }
    for (int e = i; e < EE; e += stride) {
        int d = edst[e];
        int p = atomicAdd(&g_dcur[d], 1);
        g_csrc[g_doff[d] + p] = esrc[e];
    }
}

// ---------------- weight prep + next-call counter reset ----------------
// mat 0: Wk*rel_att*(rel_pri/4), mat 1: Wq, mat 2: Wv*rel_msg, mat 3: Wa.
__global__ void k_combine(const float* __restrict__ Wk, const float* __restrict__ Wq,
                          const float* __restrict__ Wv, const float* __restrict__ Wa,
                          const float* __restrict__ rel_att, const float* __restrict__ rel_msg,
                          const float* __restrict__ rel_pri) {
    int t = blockIdx.x, mat = blockIdx.y, l = blockIdx.z;
    __shared__ float sA[NHH * DD * DD];
    __shared__ float sScl[NHH];
    const float* W = (mat == 0 ? Wk : (mat == 1 ? Wq : (mat == 2 ? Wv : Wa)))
                     + (size_t)(l * TT + t) * HH * HH;
    const float* A = (mat == 0 ? rel_att : rel_msg) + (size_t)l * NHH * DD * DD;
    __nv_bfloat16* out = g_wb + (((size_t)l * TT + t) * 4 + mat) * 32768;
    bool fold = (mat == 0 || mat == 2);
    if (fold) {
        for (int idx = threadIdx.x; idx < NHH * DD * DD; idx += blockDim.x) sA[idx] = A[idx];
        if (threadIdx.x < NHH)
            sScl[threadIdx.x] = (mat == 0) ? rel_pri[l * NHH + threadIdx.x] * 0.25f : 1.0f;
    }
    __syncthreads();
    for (int idx = threadIdx.x; idx < HH * HH; idx += blockDim.x) {
        int i = idx >> 7, c = idx & 127;
        float v;
        if (!fold) {
            v = W[i * HH + c];
        } else {
            int h = c >> 4, f = c & 15;
            float s = 0.0f;
            #pragma unroll
            for (int d = 0; d < DD; d++)
                s += W[i * HH + h * DD + d] * sA[h * DD * DD + d * DD + f];
            v = s * sScl[h];
        }
        __nv_bfloat16 hi = __float2bfloat16(v);
        __nv_bfloat16 lo = __float2bfloat16(v - __bfloat162float(hi));
        out[c * 128 + i] = hi;
        out[16384 + c * 128 + i] = lo;
    }
    // Counter reset for the next call (this kernel runs after all consumers).
    int gid = ((blockIdx.z * 4 + blockIdx.y) * TT + blockIdx.x) * blockDim.x + threadIdx.x;
    int gstr = TT * 4 * LL * blockDim.x;   // 12288
    for (int j = gid; j < NN; j += gstr) { g_dcnt[j] = 0; g_dcur[j] = 0; }
    if (gid < TT) { g_tcnt[gid] = 0; g_tcur[gid] = 0; }
}

// ---------------- mma.sync projection kernel ----------------
__global__ void __launch_bounds__(256, 2)
k_proj_mma(const float* __restrict__ ext_hidden, const float* __restrict__ xn,
           const float* __restrict__ Wpos, int l) {
    int t = blockIdx.y;
    int beg = g_toff[t], end = g_toff[t + 1];
    int base = beg + (int)blockIdx.x * 128;
    if (base >= end) return;
    int cnt = min(128, end - base);

    extern __shared__ __align__(16) char dyns[];
    __shared__ int nidx[128];
    __shared__ float sxn0[128], sxn1[128];

    int tid = threadIdx.x;
    int wid = tid >> 5, lane = tid & 31;

    u32 sbase = smem_u32(dyns);
    u32 Ahi = sbase, Alo = sbase + ATILE, Bb = sbase + 2 * ATILE;

    if (tid < 128) {
        int slot = (tid < cnt) ? tid : 0;
        int n = g_tnodes[base + slot];
        nidx[tid] = n;
        sxn0[tid] = (tid < cnt) ? xn[2 * n] : 0.f;
        sxn1[tid] = (tid < cnt) ? xn[2 * n + 1] : 0.f;
    }
    __syncthreads();

    const float* hin = (l == 0) ? ext_hidden : g_hid;
    float4 wpA = ((const float4*)(Wpos + l * 2 * HH))[lane];
    float4 wpB = ((const float4*)(Wpos + l * 2 * HH + HH))[lane];
    #pragma unroll 4
    for (int r = wid; r < 128; r += 8) {
        float4 hv = make_float4(0.f, 0.f, 0.f, 0.f);
        if (r < cnt) {
            size_t rowoff = (size_t)nidx[r] * HH;
            hv = *((const float4*)(hin + rowoff) + lane);
            float x0 = sxn0[r], x1 = sxn1[r];
            hv.x += x0 * wpA.x + x1 * wpB.x;
            hv.y += x0 * wpA.y + x1 * wpB.y;
            hv.z += x0 * wpA.z + x1 * wpB.z;
            hv.w += x0 * wpA.w + x1 * wpB.w;
            *((float4*)(g_h + rowoff) + lane) = hv;
        }
        u64 hp, lp;
        split4(hv, hp, lp);
        u32 off = (u32)r * (APITCH * 2) + (u32)lane * 8;
        *(u64*)(dyns + off) = hp;
        *(u64*)(dyns + ATILE + off) = lp;
    }

    const u64* wb64 = (const u64*)g_wb;
    int m0 = wid * 16;
    u32 aro = (u32)((m0 + (lane & 15)) * APITCH + (lane >> 4) * 8) * 2;
    // ldsm4-B lane map: lane>>4 selects nt-pair member; khalf = (lane>>3)&1; row = lane&7
    u32 bro4 = (u32)((((lane >> 4) * 8 + (lane & 7)) * APITCH) + ((lane >> 3) & 1) * 8) * 2;
    int r0 = m0 + (lane >> 2), r1 = r0 + 8;

    for (int mat = 0; mat < 3; mat++) {
        float c[16][4];
        #pragma unroll
        for (int nt = 0; nt < 16; nt++) {
            c[nt][0] = 0.f; c[nt][1] = 0.f; c[nt][2] = 0.f; c[nt][3] = 0.f;
        }
        size_t wbase = (((size_t)l * TT + t) * 4 + mat) * 8192;
        #pragma unroll
        for (int s = 0; s < 2; s++) {
            __syncthreads();
            #pragma unroll 4
            for (int j = tid; j < 4096; j += 256) {
                u64 v = wb64[wbase + s * 4096 + j];
                int n = j >> 5, k4 = j & 31;
                *(u64*)(dyns + 2 * ATILE + n * (APITCH * 2) + k4 * 8) = v;
            }
            __syncthreads();
            #pragma unroll
            for (int ks = 0; ks < 8; ks++) {
                u32 a0[4], a1[4];
                ldsm4(a0, Ahi + aro + ks * 32);
                if (s == 0) ldsm4(a1, Alo + aro + ks * 32);
                #pragma unroll
                for (int nt = 0; nt < 16; nt += 2) {
                    u32 b[4];
                    ldsm4(b, Bb + bro4 + (u32)nt * 8 * (APITCH * 2) + ks * 32);
                    mma16816(c[nt], a0, b[0], b[1]);
                    mma16816(c[nt + 1], a0, b[2], b[3]);
                    if (s == 0) {
                        mma16816(c[nt], a1, b[0], b[1]);
                        mma16816(c[nt + 1], a1, b[2], b[3]);
                    }
                }
            }
        }
        float* dst = (mat == 0) ? g_kt : (mat == 1) ? g_q : g_vm;
        #pragma unroll
        for (int nt = 0; nt < 16; nt++) {
            int col = nt * 8 + (lane & 3) * 2;
            if (r0 < cnt)
                *(float2*)(dst + (size_t)nidx[r0] * HH + col) = make_float2(c[nt][0], c[nt][1]);
            if (r1 < cnt)
                *(float2*)(dst + (size_t)nidx[r1] * HH + col) = make_float2(c[nt][2], c[nt][3]);
        }
    }
}

// ---------------- edge kernel: fp32 gathers, 2-wide unroll (R12-proven config) ----------------
__global__ void k_edge() {
    int warp = threadIdx.x >> 5, lane = threadIdx.x & 31;
    int n = blockIdx.x * 8 + warp;
    if (n >= NN) return;
    int beg = g_doff[n], end = g_doff[n + 1];
    float* outp = g_trans + (size_t)n * HH + lane * 4;
    if (beg == end) {
        *(float4*)outp = make_float4(0.f, 0.f, 0.f, 0.f);
        return;
    }
    float4 q4 = *(const float4*)(g_q + (size_t)n * HH + lane * 4);

    int src0 = g_csrc[beg];
    float4 k0 = *(const float4*)(g_kt + (size_t)src0 * HH + lane * 4);
    float4 v0 = *(const float4*)(g_vm + (size_t)src0 * HH + lane * 4);
    float C = k0.x * q4.x + k0.y * q4.y + k0.z * q4.z + k0.w * q4.w;
    C += __shfl_xor_sync(0xffffffffu, C, 1);
    C += __shfl_xor_sync(0xffffffffu, C, 2);

    float den0 = 1.0f, den1 = 0.0f;
    float ax0 = v0.x, ay0 = v0.y, az0 = v0.z, aw0 = v0.w;
    float ax1 = 0.f, ay1 = 0.f, az1 = 0.f, aw1 = 0.f;

    for (int b = beg + 1; b < end; b += 32) {
        int nchunk = min(32, end - b);
        int srcs = (b + lane < end) ? g_csrc[b + lane] : 0;
        int j = 0;
        for (; j + 2 <= nchunk; j += 2) {
            int sA = __shfl_sync(0xffffffffu, srcs, j);
            int sB = __shfl_sync(0xffffffffu, srcs, j + 1);
            float4 kA = *(const float4*)(g_kt + (size_t)sA * HH + lane * 4);
            float4 kB = *(const float4*)(g_kt + (size_t)sB * HH + lane * 4);
            float4 vA = *(const float4*)(g_vm + (size_t)sA * HH + lane * 4);
            float4 vB = *(const float4*)(g_vm + (size_t)sB * HH + lane * 4);
            float sa = kA.x * q4.x + kA.y * q4.y + kA.z * q4.z + kA.w * q4.w;
            float sb = kB.x * q4.x + kB.y * q4.y + kB.z * q4.z + kB.w * q4.w;
            sa += __shfl_xor_sync(0xffffffffu, sa, 1);
            sb += __shfl_xor_sync(0xffffffffu, sb, 1);
            sa += __shfl_xor_sync(0xffffffffu, sa, 2);
            sb += __shfl_xor_sync(0xffffffffu, sb, 2);
            float pa = __expf(sa - C);
            float pb = __expf(sb - C);
            den0 += pa;             den1 += pb;
            ax0 += pa * vA.x;       ax1 += pb * vB.x;
            ay0 += pa * vA.y;       ay1 += pb * vB.y;
            az0 += pa * vA.z;       az1 += pb * vB.z;
            aw0 += pa * vA.w;       aw1 += pb * vB.w;
        }
        if (j < nchunk) {
            int sA = __shfl_sync(0xffffffffu, srcs, j);
            float4 kA = *(const float4*)(g_kt + (size_t)sA * HH + lane * 4);
            float4 vA = *(const float4*)(g_vm + (size_t)sA * HH + lane * 4);
            float sa = kA.x * q4.x + kA.y * q4.y + kA.z * q4.z + kA.w * q4.w;
            sa += __shfl_xor_sync(0xffffffffu, sa, 1);
            sa += __shfl_xor_sync(0xffffffffu, sa, 2);
            float pa = __expf(sa - C);
            den0 += pa;
            ax0 += pa * vA.x; ay0 += pa * vA.y;
            az0 += pa * vA.z; aw0 += pa * vA.w;
        }
    }
    float inv = 1.0f / (den0 + den1 + 1e-16f);
    float4 o;
    o.x = geluf((ax0 + ax1) * inv);
    o.y = geluf((ay0 + ay1) * inv);
    o.z = geluf((az0 + az1) * inv);
    o.w = geluf((aw0 + aw1) * inv);
    *(float4*)outp = o;
}

// ---------------- mma.sync output kernel: out = trans @ Wa[t] + fused epilogue ----------------
__global__ void __launch_bounds__(256, 2)
k_out_mma(const float* __restrict__ skip,
          const float* __restrict__ ext_cn, const float* __restrict__ ext_hidden,
          const float* __restrict__ w_pri,
          float* __restrict__ out_cn, float* __restrict__ out_hid,
          float* __restrict__ out_pri, int l) {
    int t = blockIdx.y;
    int beg = g_toff[t], end = g_toff[t + 1];
    int base = beg + (int)blockIdx.x * 128;
    if (base >= end) return;
    int cnt = min(128, end - base);

    extern __shared__ __align__(16) char dyns[];
    __shared__ int nidx[128];
    __shared__ float ssk;
    __shared__ float swpri[128];

    int tid = threadIdx.x;
    int wid = tid >> 5, lane = tid & 31;

    u32 sbase = smem_u32(dyns);
    u32 Ahi = sbase, Alo = sbase + ATILE, Bb = sbase + 2 * ATILE;

    if (tid < 128) {
        nidx[tid] = g_tnodes[base + ((tid < cnt) ? tid : 0)];
        swpri[tid] = (l == LL - 1) ? w_pri[l * HH + tid] : 0.f;
    }
    if (tid == 0) ssk = 1.0f / (1.0f + __expf(-skip[l * TT + t]));
    __syncthreads();

    #pragma unroll 4
    for (int r = wid; r < 128; r += 8) {
        float4 hv = make_float4(0.f, 0.f, 0.f, 0.f);
        if (r < cnt)
            hv = *((const float4*)(g_trans + (size_t)nidx[r] * HH) + lane);
        u64 hp, lp;
        split4(hv, hp, lp);
        u32 off = (u32)r * (APITCH * 2) + (u32)lane * 8;
        *(u64*)(dyns + off) = hp;
        *(u64*)(dyns + ATILE + off) = lp;
    }

    const u64* wb64 = (const u64*)g_wb;
    int m0 = wid * 16;
    u32 aro = (u32)((m0 + (lane & 15)) * APITCH + (lane >> 4) * 8) * 2;
    u32 bro4 = (u32)((((lane >> 4) * 8 + (lane & 7)) * APITCH) + ((lane >> 3) & 1) * 8) * 2;
    int r0 = m0 + (lane >> 2), r1 = r0 + 8;

    float c[16][4];
    #pragma unroll
    for (int nt = 0; nt < 16; nt++) {
        c[nt][0] = 0.f; c[nt][1] = 0.f; c[nt][2] = 0.f; c[nt][3] = 0.f;
    }
    size_t wbase = (((size_t)l * TT + t) * 4 + 3) * 8192;   // mat 3 = Wa
    #pragma unroll
    for (int s = 0; s < 2; s++) {
        __syncthreads();
        #pragma unroll 4
        for (int j = tid; j < 4096; j += 256) {
            u64 v = wb64[wbase + s * 4096 + j];
            int n = j >> 5, k4 = j & 31;
            *(u64*)(dyns + 2 * ATILE + n * (APITCH * 2) + k4 * 8) = v;
        }
        __syncthreads();
        #pragma unroll
        for (int ks = 0; ks < 8; ks++) {
            u32 a0[4], a1[4];
            ldsm4(a0, Ahi + aro + ks * 32);
            if (s == 0) ldsm4(a1, Alo + aro + ks * 32);
            #pragma unroll
            for (int nt = 0; nt < 16; nt += 2) {
                u32 b[4];
                ldsm4(b, Bb + bro4 + (u32)nt * 8 * (APITCH * 2) + ks * 32);
                mma16816(c[nt], a0, b[0], b[1]);
                mma16816(c[nt + 1], a0, b[2], b[3]);
                if (s == 0) {
                    mma16816(c[nt], a1, b[0], b[1]);
                    mma16816(c[nt + 1], a1, b[2], b[3]);
                }
            }
        }
    }

    const float* cn_in = (l == 0) ? ext_cn : g_cn;
    const float* hid_in = (l == 0) ? ext_hidden : g_hid;
    float* cn_o = (l == LL - 1) ? out_cn : g_cn;
    float* hid_o = (l == LL - 1) ? out_hid : g_hid;
    float sk = ssk, omsk = 1.0f - ssk;
    float pri0 = 0.f, pri1 = 0.f;
    size_t off0 = (size_t)nidx[r0 < cnt ? r0 : 0] * HH;
    size_t off1 = (size_t)nidx[r1 < cnt ? r1 : 0] * HH;
    #pragma unroll
    for (int nt = 0; nt < 16; nt++) {
        int col = nt * 8 + (lane & 3) * 2;
        if (r0 < cnt) {
            float2 hh = *(const float2*)(g_h + off0 + col);
            float2 cc = *(const float2*)(cn_in + off0 + col);
            float2 dd = *(const float2*)(hid_in + off0 + col);
            float hgx = sk * c[nt][0] + omsk * hh.x;
            float hgy = sk * c[nt][1] + omsk * hh.y;
            float cnx = hgx + cc.x, cny = hgy + cc.y;
            *(float2*)(cn_o + off0 + col) = make_float2(cnx, cny);
            *(float2*)(hid_o + off0 + col) = make_float2(dd.x + tanhf(cnx), dd.y + tanhf(cny));
            pri0 += hgx * swpri[col] + hgy * swpri[col + 1];
        }
        if (r1 < cnt) {
            float2 hh = *(const float2*)(g_h + off1 + col);
            float2 cc = *(const float2*)(cn_in + off1 + col);
            float2 dd = *(const float2*)(hid_in + off1 + col);
            float hgx = sk * c[nt][2] + omsk * hh.x;
            float hgy = sk * c[nt][3] + omsk * hh.y;
            float cnx = hgx + cc.x, cny = hgy + cc.y;
            *(float2*)(cn_o + off1 + col) = make_float2(cnx, cny);
            *(float2*)(hid_o + off1 + col) = make_float2(dd.x + tanhf(cnx), dd.y + tanhf(cny));
            pri1 += hgx * swpri[col] + hgy * swpri[col + 1];
        }
    }
    if (l == LL - 1) {
        pri0 += __shfl_xor_sync(0xffffffffu, pri0, 1);
        pri0 += __shfl_xor_sync(0xffffffffu, pri0, 2);
        pri1 += __shfl_xor_sync(0xffffffffu, pri1, 1);
        pri1 += __shfl_xor_sync(0xffffffffu, pri1, 2);
        if ((lane & 3) == 0) {
            if (r0 < cnt) out_pri[nidx[r0]] = 1.0f / (1.0f + __expf(-pri0));
            if (r1 < cnt) out_pri[nidx[r1]] = 1.0f / (1.0f + __expf(-pri1));
        }
    }
}

// ---------------- launch ----------------
extern "C" void kernel_launch(void* const* d_in, const int* in_sizes, int n_in,
                              void* d_out, int out_size) {
    const float* in_hidden = (const float*)d_in[0];
    const float* in_cn     = (const float*)d_in[1];
    const float* in_x      = (const float*)d_in[2];
    const int*   node_type = (const int*)d_in[3];
    const int*   edge_src  = (const int*)d_in[4];
    const int*   edge_dst  = (const int*)d_in[5];
    const float* W_pos     = (const float*)d_in[6];
    const float* Wk        = (const float*)d_in[7];
    const float* Wq        = (const float*)d_in[8];
    const float* Wv        = (const float*)d_in[9];
    const float* Wa        = (const float*)d_in[10];
    const float* rel_att   = (const float*)d_in[11];
    const float* rel_msg   = (const float*)d_in[12];
    const float* rel_pri   = (const float*)d_in[13];
    const float* skip      = (const float*)d_in[14];
    const float* w_pri     = (const float*)d_in[15];

    float* out = (float*)d_out;
    float* out_hid = out;
    float* out_cn = out + (size_t)NN * HH;
    float* out_pri = out + (size_t)2 * NN * HH;

    cudaFuncSetAttribute(k_proj_mma, cudaFuncAttributeMaxDynamicSharedMemorySize, DSMEM_MMA);
    cudaFuncSetAttribute(k_out_mma, cudaFuncAttributeMaxDynamicSharedMemorySize, DSMEM_MMA);

    int nchunks = (NN + 1023) / 1024;  // 49

    k_count<<<1568, 256>>>(edge_dst, node_type);
    k_scanA<<<nchunks, 1024>>>();
    k_scanC<<<196, 256>>>(nchunks);
    k_scatter<<<1568, 256>>>(node_type, edge_src, edge_dst);
    k_combine<<<dim3(TT, 4, LL), 256>>>(Wk, Wq, Wv, Wa, rel_att, rel_msg, rel_pri);

    int tiles128 = (NN + 127) / 128;
    int nodeblk = (NN + 7) / 8;

    for (int l = 0; l < LL; l++) {
        k_proj_mma<<<dim3(tiles128, TT), 256, DSMEM_MMA>>>(in_hidden, in_x, W_pos, l);
        k_edge<<<nodeblk, 256>>>();
        k_out_mma<<<dim3(tiles128, TT), 256, DSMEM_MMA>>>(skip, in_cn, in_hidden, w_pri,
                                                          out_cn, out_hid, out_pri, l);
    }
}

// round 16
// speedup vs baseline: 1.0763x; 1.0129x over previous
#include <cuda_runtime.h>
#include <cuda_bf16.h>
#include <math.h>

#define NN 50000
#define EE 800000
#define HH 128
#define NHH 8
#define DD 16
#define TT 6
#define LL 2

#define APITCH 136                     // bf16 elems per smem row (272 B: conflict-free ldmatrix)
#define ATILE (128 * APITCH * 2)       // bytes per 128x128 bf16 tile with pitch = 34816
#define DSMEM_MMA (3 * ATILE)          // Ahi, Alo, B(single split buffer) = 104448 B -> 2 CTA/SM

typedef unsigned long long u64;
typedef unsigned int u32;

// ---------------- scratch (device globals; no allocation allowed) ----------------
__device__ float g_h[NN * HH];
__device__ float g_kt[NN * HH];
__device__ float g_q[NN * HH];
__device__ float g_vm[NN * HH];
__device__ float g_trans[NN * HH];
__device__ float g_hid[NN * HH];
__device__ float g_cn[NN * HH];
// bf16 split weights per (l,t,mat 0..3): [split2][n128][k128] = 32768 bf16 (65536 B)
__device__ __align__(16) __nv_bfloat16 g_wb[(size_t)LL * TT * 4 * 32768];
__device__ int g_tcnt[TT];
__device__ int g_toff[TT + 1];
__device__ int g_tcur[TT];
__device__ int g_tnodes[NN];
__device__ int g_dcnt[NN];
__device__ int g_doff[NN + 1];
__device__ int g_dcur[NN];
__device__ int g_csrc[EE];
__device__ int g_bsum[64];

// ---------------- helpers ----------------
__device__ __forceinline__ float geluf(float x) {
    float x3 = x * x * x;
    return 0.5f * x * (1.0f + tanhf(0.7978845608028654f * (x + 0.044715f * x3)));
}
__device__ __forceinline__ u32 smem_u32(const void* p) {
    u32 a;
    asm("{ .reg .u64 t; cvta.to.shared.u64 t, %1; cvt.u32.u64 %0, t; }" : "=r"(a) : "l"(p));
    return a;
}
__device__ __forceinline__ void ldsm4(u32* r, u32 addr) {
    asm volatile("ldmatrix.sync.aligned.m8n8.x4.shared.b16 {%0,%1,%2,%3}, [%4];"
                 : "=r"(r[0]), "=r"(r[1]), "=r"(r[2]), "=r"(r[3]) : "r"(addr));
}
__device__ __forceinline__ void ldsm2(u32& r0, u32& r1, u32 addr) {
    asm volatile("ldmatrix.sync.aligned.m8n8.x2.shared.b16 {%0,%1}, [%2];"
                 : "=r"(r0), "=r"(r1) : "r"(addr));
}
__device__ __forceinline__ void mma16816(float* c, const u32* a, u32 b0, u32 b1) {
    asm volatile(
        "mma.sync.aligned.m16n8k16.row.col.f32.bf16.bf16.f32 "
        "{%0,%1,%2,%3}, {%4,%5,%6,%7}, {%8,%9}, {%0,%1,%2,%3};"
        : "+f"(c[0]), "+f"(c[1]), "+f"(c[2]), "+f"(c[3])
        : "r"(a[0]), "r"(a[1]), "r"(a[2]), "r"(a[3]), "r"(b0), "r"(b1));
}
// split fp32x4 -> packed bf16 hi/lo u64s
__device__ __forceinline__ void split4(float4 hv, u64& hp, u64& lp) {
    __nv_bfloat16 h0 = __float2bfloat16(hv.x), h1 = __float2bfloat16(hv.y),
                  h2 = __float2bfloat16(hv.z), h3 = __float2bfloat16(hv.w);
    __nv_bfloat16 l0 = __float2bfloat16(hv.x - __bfloat162float(h0));
    __nv_bfloat16 l1 = __float2bfloat16(hv.y - __bfloat162float(h1));
    __nv_bfloat16 l2 = __float2bfloat16(hv.z - __bfloat162float(h2));
    __nv_bfloat16 l3 = __float2bfloat16(hv.w - __bfloat16_as_ushort(h3) * 0.0f - __bfloat162float(h3));
    hp = ((u64)((((u32)__bfloat16_as_ushort(h3)) << 16) | __bfloat16_as_ushort(h2)) << 32)
         | ((((u32)__bfloat16_as_ushort(h1)) << 16) | __bfloat16_as_ushort(h0));
    lp = ((u64)((((u32)__bfloat16_as_ushort(l3)) << 16) | __bfloat16_as_ushort(l2)) << 32)
         | ((((u32)__bfloat16_as_ushort(l1)) << 16) | __bfloat16_as_ushort(l0));
}

// ---------------- setup kernels ----------------
// k_zero is gone: k_combine zeroes dcnt/dcur/tcnt/tcur for the NEXT call
// (device globals are statically zero-initialized, so call 1 is also correct).

__global__ void k_count(const int* __restrict__ edst, const int* __restrict__ nt) {
    __shared__ int sh[TT];
    int tid = threadIdx.x;
    if (tid < TT) sh[tid] = 0;
    __syncthreads();
    int i = blockIdx.x * blockDim.x + tid;
    int stride = gridDim.x * blockDim.x;
    for (int e = i; e < EE; e += stride) atomicAdd(&g_dcnt[edst[e]], 1);
    for (int n = i; n < NN; n += stride) atomicAdd(&sh[nt[n]], 1);
    __syncthreads();
    if (tid < TT) atomicAdd(&g_tcnt[tid], sh[tid]);
}

__global__ void k_scanA() {
    __shared__ int wsum[32];
    int b = blockIdx.x, tid = threadIdx.x, lane = tid & 31, wid = tid >> 5;
    int i = b * 1024 + tid;
    int v = (i < NN) ? g_dcnt[i] : 0;
    int x = v;
    #pragma unroll
    for (int o = 1; o < 32; o <<= 1) {
        int y = __shfl_up_sync(0xffffffffu, x, o);
        if (lane >= o) x += y;
    }
    if (lane == 31) wsum[wid] = x;
    __syncthreads();
    if (wid == 0) {
        int w = wsum[lane];
        #pragma unroll
        for (int o = 1; o < 32; o <<= 1) {
            int y = __shfl_up_sync(0xffffffffu, w, o);
            if (lane >= o) w += y;
        }
        wsum[lane] = w;
    }
    __syncthreads();
    int incl = x + (wid > 0 ? wsum[wid - 1] : 0);
    if (i < NN) g_doff[i] = incl - v;
    if (tid == 1023) g_bsum[b] = incl;
}

// scanC: per-block redundant 64-wide scan of chunk totals; adds base; block 0
// also writes doff[NN] and the type offsets.
__global__ void k_scanC(int nchunks) {
    __shared__ int schunk[64];
    __shared__ int wtot[2];
    int tid = threadIdx.x;
    int lane = tid & 31;
    if (tid < 64) {
        int v = (tid < nchunks) ? g_bsum[tid] : 0;
        int x = v;
        #pragma unroll
        for (int o = 1; o < 32; o <<= 1) {
            int y = __shfl_up_sync(0xffffffffu, x, o);
            if (lane >= o) x += y;
        }
        if (lane == 31) wtot[tid >> 5] = x;
        schunk[tid] = x - v;   // exclusive within warp
    }
    __syncthreads();
    if (tid >= 32 && tid < 64) schunk[tid] += wtot[0];
    __syncthreads();
    int i = blockIdx.x * blockDim.x + tid;
    if (i < NN) g_doff[i] += schunk[i >> 10];
    if (blockIdx.x == 0 && tid == 0) {
        g_doff[NN] = wtot[0] + wtot[1];
        int r = 0;
        for (int t = 0; t < TT; t++) { g_toff[t] = r; r += g_tcnt[t]; }
        g_toff[TT] = r;
    }
}

__global__ void k_scatter(const int* __restrict__ nt, const int* __restrict__ esrc,
                          const int* __restrict__ edst) {
    int i = blockIdx.x * blockDim.x + threadIdx.x;
    int stride = gridDim.x * blockDim.x;
    for (int n = i; n < NN; n += stride) {
        int t = nt[n];
        int p = atomicAdd(&g_tcur[t], 1);
        g_tnodes[g_toff[t] + p] = n;
    }
    for (int e = i; e < EE; e += stride) {
        int d = edst[e];
        int p = atomicAdd(&g_dcur[d], 1);
        g_csrc[g_doff[d] + p] = esrc[e];
    }
}

// ---------------- weight prep + next-call counter reset ----------------
// mat 0: Wk*rel_att*(rel_pri/4), mat 1: Wq, mat 2: Wv*rel_msg, mat 3: Wa.
__global__ void k_combine(const float* __restrict__ Wk, const float* __restrict__ Wq,
                          const float* __restrict__ Wv, const float* __restrict__ Wa,
                          const float* __restrict__ rel_att, const float* __restrict__ rel_msg,
                          const float* __restrict__ rel_pri) {
    int t = blockIdx.x, mat = blockIdx.y, l = blockIdx.z;
    __shared__ float sA[NHH * DD * DD];
    __shared__ float sScl[NHH];
    const float* W = (mat == 0 ? Wk : (mat == 1 ? Wq : (mat == 2 ? Wv : Wa)))
                     + (size_t)(l * TT + t) * HH * HH;
    const float* A = (mat == 0 ? rel_att : rel_msg) + (size_t)l * NHH * DD * DD;
    __nv_bfloat16* out = g_wb + (((size_t)l * TT + t) * 4 + mat) * 32768;
    bool fold = (mat == 0 || mat == 2);
    if (fold) {
        for (int idx = threadIdx.x; idx < NHH * DD * DD; idx += blockDim.x) sA[idx] = A[idx];
        if (threadIdx.x < NHH)
            sScl[threadIdx.x] = (mat == 0) ? rel_pri[l * NHH + threadIdx.x] * 0.25f : 1.0f;
    }
    __syncthreads();
    for (int idx = threadIdx.x; idx < HH * HH; idx += blockDim.x) {
        int i = idx >> 7, c = idx & 127;
        float v;
        if (!fold) {
            v = W[i * HH + c];
        } else {
            int h = c >> 4, f = c & 15;
            float s = 0.0f;
            #pragma unroll
            for (int d = 0; d < DD; d++)
                s += W[i * HH + h * DD + d] * sA[h * DD * DD + d * DD + f];
            v = s * sScl[h];
        }
        __nv_bfloat16 hi = __float2bfloat16(v);
        __nv_bfloat16 lo = __float2bfloat16(v - __bfloat162float(hi));
        out[c * 128 + i] = hi;
        out[16384 + c * 128 + i] = lo;
    }
    // Counter reset for the next call (this kernel runs after all consumers).
    int gid = ((blockIdx.z * 4 + blockIdx.y) * TT + blockIdx.x) * blockDim.x + threadIdx.x;
    int gstr = TT * 4 * LL * blockDim.x;   // 12288
    for (int j = gid; j < NN; j += gstr) { g_dcnt[j] = 0; g_dcur[j] = 0; }
    if (gid < TT) { g_tcnt[gid] = 0; g_tcur[gid] = 0; }
}

// ---------------- mma.sync projection kernel (R12-exact: ldsm2-B) ----------------
__global__ void __launch_bounds__(256, 2)
k_proj_mma(const float* __restrict__ ext_hidden, const float* __restrict__ xn,
           const float* __restrict__ Wpos, int l) {
    int t = blockIdx.y;
    int beg = g_toff[t], end = g_toff[t + 1];
    int base = beg + (int)blockIdx.x * 128;
    if (base >= end) return;
    int cnt = min(128, end - base);

    extern __shared__ __align__(16) char dyns[];
    __shared__ int nidx[128];
    __shared__ float sxn0[128], sxn1[128];

    int tid = threadIdx.x;
    int wid = tid >> 5, lane = tid & 31;

    u32 sbase = smem_u32(dyns);
    u32 Ahi = sbase, Alo = sbase + ATILE, Bb = sbase + 2 * ATILE;

    if (tid < 128) {
        int slot = (tid < cnt) ? tid : 0;
        int n = g_tnodes[base + slot];
        nidx[tid] = n;
        sxn0[tid] = (tid < cnt) ? xn[2 * n] : 0.f;
        sxn1[tid] = (tid < cnt) ? xn[2 * n + 1] : 0.f;
    }
    __syncthreads();

    const float* hin = (l == 0) ? ext_hidden : g_hid;
    float4 wpA = ((const float4*)(Wpos + l * 2 * HH))[lane];
    float4 wpB = ((const float4*)(Wpos + l * 2 * HH + HH))[lane];
    #pragma unroll 4
    for (int r = wid; r < 128; r += 8) {
        float4 hv = make_float4(0.f, 0.f, 0.f, 0.f);
        if (r < cnt) {
            size_t rowoff = (size_t)nidx[r] * HH;
            hv = *((const float4*)(hin + rowoff) + lane);
            float x0 = sxn0[r], x1 = sxn1[r];
            hv.x += x0 * wpA.x + x1 * wpB.x;
            hv.y += x0 * wpA.y + x1 * wpB.y;
            hv.z += x0 * wpA.z + x1 * wpB.z;
            hv.w += x0 * wpA.w + x1 * wpB.w;
            *((float4*)(g_h + rowoff) + lane) = hv;
        }
        __nv_bfloat16 h0 = __float2bfloat16(hv.x), h1 = __float2bfloat16(hv.y),
                      h2 = __float2bfloat16(hv.z), h3 = __float2bfloat16(hv.w);
        __nv_bfloat16 l0 = __float2bfloat16(hv.x - __bfloat162float(h0));
        __nv_bfloat16 l1 = __float2bfloat16(hv.y - __bfloat162float(h1));
        __nv_bfloat16 l2 = __float2bfloat16(hv.z - __bfloat162float(h2));
        __nv_bfloat16 l3 = __float2bfloat16(hv.w - __bfloat162float(h3));
        u64 hp = ((u64)((((u32)__bfloat16_as_ushort(h3)) << 16) | __bfloat16_as_ushort(h2)) << 32)
                 | ((((u32)__bfloat16_as_ushort(h1)) << 16) | __bfloat16_as_ushort(h0));
        u64 lp = ((u64)((((u32)__bfloat16_as_ushort(l3)) << 16) | __bfloat16_as_ushort(l2)) << 32)
                 | ((((u32)__bfloat16_as_ushort(l1)) << 16) | __bfloat16_as_ushort(l0));
        u32 off = (u32)r * (APITCH * 2) + (u32)lane * 8;
        *(u64*)(dyns + off) = hp;
        *(u64*)(dyns + ATILE + off) = lp;
    }

    const u64* wb64 = (const u64*)g_wb;
    int m0 = wid * 16;
    u32 aro = (u32)((m0 + (lane & 15)) * APITCH + (lane >> 4) * 8) * 2;
    u32 bro = (u32)(((lane & 7)) * APITCH + ((lane >> 3) & 1) * 8) * 2;
    int r0 = m0 + (lane >> 2), r1 = r0 + 8;

    for (int mat = 0; mat < 3; mat++) {
        float c[16][4];
        #pragma unroll
        for (int nt = 0; nt < 16; nt++) {
            c[nt][0] = 0.f; c[nt][1] = 0.f; c[nt][2] = 0.f; c[nt][3] = 0.f;
        }
        size_t wbase = (((size_t)l * TT + t) * 4 + mat) * 8192;
        #pragma unroll
        for (int s = 0; s < 2; s++) {
            __syncthreads();
            #pragma unroll 4
            for (int j = tid; j < 4096; j += 256) {
                u64 v = wb64[wbase + s * 4096 + j];
                int n = j >> 5, k4 = j & 31;
                *(u64*)(dyns + 2 * ATILE + n * (APITCH * 2) + k4 * 8) = v;
            }
            __syncthreads();
            #pragma unroll
            for (int ks = 0; ks < 8; ks++) {
                u32 a0[4], a1[4];
                ldsm4(a0, Ahi + aro + ks * 32);
                if (s == 0) ldsm4(a1, Alo + aro + ks * 32);
                #pragma unroll
                for (int nt = 0; nt < 16; nt++) {
                    u32 b0, b1;
                    ldsm2(b0, b1, Bb + bro + (u32)nt * 8 * (APITCH * 2) + ks * 32);
                    mma16816(c[nt], a0, b0, b1);
                    if (s == 0) mma16816(c[nt], a1, b0, b1);
                }
            }
        }
        float* dst = (mat == 0) ? g_kt : (mat == 1) ? g_q : g_vm;
        #pragma unroll
        for (int nt = 0; nt < 16; nt++) {
            int col = nt * 8 + (lane & 3) * 2;
            if (r0 < cnt)
                *(float2*)(dst + (size_t)nidx[r0] * HH + col) = make_float2(c[nt][0], c[nt][1]);
            if (r1 < cnt)
                *(float2*)(dst + (size_t)nidx[r1] * HH + col) = make_float2(c[nt][2], c[nt][3]);
        }
    }
}

// ---------------- edge kernel: fp32 gathers, 2-wide unroll (R12-proven config) ----------------
__global__ void k_edge() {
    int warp = threadIdx.x >> 5, lane = threadIdx.x & 31;
    int n = blockIdx.x * 8 + warp;
    if (n >= NN) return;
    int beg = g_doff[n], end = g_doff[n + 1];
    float* outp = g_trans + (size_t)n * HH + lane * 4;
    if (beg == end) {
        *(float4*)outp = make_float4(0.f, 0.f, 0.f, 0.f);
        return;
    }
    float4 q4 = *(const float4*)(g_q + (size_t)n * HH + lane * 4);

    int src0 = g_csrc[beg];
    float4 k0 = *(const float4*)(g_kt + (size_t)src0 * HH + lane * 4);
    float4 v0 = *(const float4*)(g_vm + (size_t)src0 * HH + lane * 4);
    float C = k0.x * q4.x + k0.y * q4.y + k0.z * q4.z + k0.w * q4.w;
    C += __shfl_xor_sync(0xffffffffu, C, 1);
    C += __shfl_xor_sync(0xffffffffu, C, 2);

    float den0 = 1.0f, den1 = 0.0f;
    float ax0 = v0.x, ay0 = v0.y, az0 = v0.z, aw0 = v0.w;
    float ax1 = 0.f, ay1 = 0.f, az1 = 0.f, aw1 = 0.f;

    for (int b = beg + 1; b < end; b += 32) {
        int nchunk = min(32, end - b);
        int srcs = (b + lane < end) ? g_csrc[b + lane] : 0;
        int j = 0;
        for (; j + 2 <= nchunk; j += 2) {
            int sA = __shfl_sync(0xffffffffu, srcs, j);
            int sB = __shfl_sync(0xffffffffu, srcs, j + 1);
            float4 kA = *(const float4*)(g_kt + (size_t)sA * HH + lane * 4);
            float4 kB = *(const float4*)(g_kt + (size_t)sB * HH + lane * 4);
            float4 vA = *(const float4*)(g_vm + (size_t)sA * HH + lane * 4);
            float4 vB = *(const float4*)(g_vm + (size_t)sB * HH + lane * 4);
            float sa = kA.x * q4.x + kA.y * q4.y + kA.z * q4.z + kA.w * q4.w;
            float sb = kB.x * q4.x + kB.y * q4.y + kB.z * q4.z + kB.w * q4.w;
            sa += __shfl_xor_sync(0xffffffffu, sa, 1);
            sb += __shfl_xor_sync(0xffffffffu, sb, 1);
            sa += __shfl_xor_sync(0xffffffffu, sa, 2);
            sb += __shfl_xor_sync(0xffffffffu, sb, 2);
            float pa = __expf(sa - C);
            float pb = __expf(sb - C);
            den0 += pa;             den1 += pb;
            ax0 += pa * vA.x;       ax1 += pb * vB.x;
            ay0 += pa * vA.y;       ay1 += pb * vB.y;
            az0 += pa * vA.z;       az1 += pb * vB.z;
            aw0 += pa * vA.w;       aw1 += pb * vB.w;
        }
        if (j < nchunk) {
            int sA = __shfl_sync(0xffffffffu, srcs, j);
            float4 kA = *(const float4*)(g_kt + (size_t)sA * HH + lane * 4);
            float4 vA = *(const float4*)(g_vm + (size_t)sA * HH + lane * 4);
            float sa = kA.x * q4.x + kA.y * q4.y + kA.z * q4.z + kA.w * q4.w;
            sa += __shfl_xor_sync(0xffffffffu, sa, 1);
            sa += __shfl_xor_sync(0xffffffffu, sa, 2);
            float pa = __expf(sa - C);
            den0 += pa;
            ax0 += pa * vA.x; ay0 += pa * vA.y;
            az0 += pa * vA.z; aw0 += pa * vA.w;
        }
    }
    float inv = 1.0f / (den0 + den1 + 1e-16f);
    float4 o;
    o.x = geluf((ax0 + ax1) * inv);
    o.y = geluf((ay0 + ay1) * inv);
    o.z = geluf((az0 + az1) * inv);
    o.w = geluf((aw0 + aw1) * inv);
    *(float4*)outp = o;
}

// ---------------- mma.sync output kernel (R12-exact ldsm2-B) + fused epilogue ----------------
__global__ void __launch_bounds__(256, 2)
k_out_mma(const float* __restrict__ skip,
          const float* __restrict__ ext_cn, const float* __restrict__ ext_hidden,
          const float* __restrict__ w_pri,
          float* __restrict__ out_cn, float* __restrict__ out_hid,
          float* __restrict__ out_pri, int l) {
    int t = blockIdx.y;
    int beg = g_toff[t], end = g_toff[t + 1];
    int base = beg + (int)blockIdx.x * 128;
    if (base >= end) return;
    int cnt = min(128, end - base);

    extern __shared__ __align__(16) char dyns[];
    __shared__ int nidx[128];
    __shared__ float ssk;
    __shared__ float swpri[128];

    int tid = threadIdx.x;
    int wid = tid >> 5, lane = tid & 31;

    u32 sbase = smem_u32(dyns);
    u32 Ahi = sbase, Alo = sbase + ATILE, Bb = sbase + 2 * ATILE;

    if (tid < 128) {
        nidx[tid] = g_tnodes[base + ((tid < cnt) ? tid : 0)];
        swpri[tid] = (l == LL - 1) ? w_pri[l * HH + tid] : 0.f;
    }
    if (tid == 0) ssk = 1.0f / (1.0f + __expf(-skip[l * TT + t]));
    __syncthreads();

    #pragma unroll 4
    for (int r = wid; r < 128; r += 8) {
        float4 hv = make_float4(0.f, 0.f, 0.f, 0.f);
        if (r < cnt)
            hv = *((const float4*)(g_trans + (size_t)nidx[r] * HH) + lane);
        __nv_bfloat16 h0 = __float2bfloat16(hv.x), h1 = __float2bfloat16(hv.y),
                      h2 = __float2bfloat16(hv.z), h3 = __float2bfloat16(hv.w);
        __nv_bfloat16 l0 = __float2bfloat16(hv.x - __bfloat162float(h0));
        __nv_bfloat16 l1 = __float2bfloat16(hv.y - __bfloat162float(h1));
        __nv_bfloat16 l2 = __float2bfloat16(hv.z - __bfloat162float(h2));
        __nv_bfloat16 l3 = __float2bfloat16(hv.w - __bfloat162float(h3));
        u64 hp = ((u64)((((u32)__bfloat16_as_ushort(h3)) << 16) | __bfloat16_as_ushort(h2)) << 32)
                 | ((((u32)__bfloat16_as_ushort(h1)) << 16) | __bfloat16_as_ushort(h0));
        u64 lp = ((u64)((((u32)__bfloat16_as_ushort(l3)) << 16) | __bfloat16_as_ushort(l2)) << 32)
                 | ((((u32)__bfloat16_as_ushort(l1)) << 16) | __bfloat16_as_ushort(l0));
        u32 off = (u32)r * (APITCH * 2) + (u32)lane * 8;
        *(u64*)(dyns + off) = hp;
        *(u64*)(dyns + ATILE + off) = lp;
    }

    const u64* wb64 = (const u64*)g_wb;
    int m0 = wid * 16;
    u32 aro = (u32)((m0 + (lane & 15)) * APITCH + (lane >> 4) * 8) * 2;
    u32 bro = (u32)(((lane & 7)) * APITCH + ((lane >> 3) & 1) * 8) * 2;
    int r0 = m0 + (lane >> 2), r1 = r0 + 8;

    float c[16][4];
    #pragma unroll
    for (int nt = 0; nt < 16; nt++) {
        c[nt][0] = 0.f; c[nt][1] = 0.f; c[nt][2] = 0.f; c[nt][3] = 0.f;
    }
    size_t wbase = (((size_t)l * TT + t) * 4 + 3) * 8192;   // mat 3 = Wa
    #pragma unroll
    for (int s = 0; s < 2; s++) {
        __syncthreads();
        #pragma unroll 4
        for (int j = tid; j < 4096; j += 256) {
            u64 v = wb64[wbase + s * 4096 + j];
            int n = j >> 5, k4 = j & 31;
            *(u64*)(dyns + 2 * ATILE + n * (APITCH * 2) + k4 * 8) = v;
        }
        __syncthreads();
        #pragma unroll
        for (int ks = 0; ks < 8; ks++) {
            u32 a0[4], a1[4];
            ldsm4(a0, Ahi + aro + ks * 32);
            if (s == 0) ldsm4(a1, Alo + aro + ks * 32);
            #pragma unroll
            for (int nt = 0; nt < 16; nt++) {
                u32 b0, b1;
                ldsm2(b0, b1, Bb + bro + (u32)nt * 8 * (APITCH * 2) + ks * 32);
                mma16816(c[nt], a0, b0, b1);
                if (s == 0) mma16816(c[nt], a1, b0, b1);
            }
        }
    }

    const float* cn_in = (l == 0) ? ext_cn : g_cn;
    const float* hid_in = (l == 0) ? ext_hidden : g_hid;
    float* cn_o = (l == LL - 1) ? out_cn : g_cn;
    float* hid_o = (l == LL - 1) ? out_hid : g_hid;
    float sk = ssk, omsk = 1.0f - ssk;
    float pri0 = 0.f, pri1 = 0.f;
    size_t off0 = (size_t)nidx[r0 < cnt ? r0 : 0] * HH;
    size_t off1 = (size_t)nidx[r1 < cnt ? r1 : 0] * HH;
    #pragma unroll
    for (int nt = 0; nt < 16; nt++) {
        int col = nt * 8 + (lane & 3) * 2;
        if (r0 < cnt) {
            float2 hh = *(const float2*)(g_h + off0 + col);
            float2 cc = *(const float2*)(cn_in + off0 + col);
            float2 dd = *(const float2*)(hid_in + off0 + col);
            float hgx = sk * c[nt][0] + omsk * hh.x;
            float hgy = sk * c[nt][1] + omsk * hh.y;
            float cnx = hgx + cc.x, cny = hgy + cc.y;
            *(float2*)(cn_o + off0 + col) = make_float2(cnx, cny);
            *(float2*)(hid_o + off0 + col) = make_float2(dd.x + tanhf(cnx), dd.y + tanhf(cny));
            pri0 += hgx * swpri[col] + hgy * swpri[col + 1];
        }
        if (r1 < cnt) {
            float2 hh = *(const float2*)(g_h + off1 + col);
            float2 cc = *(const float2*)(cn_in + off1 + col);
            float2 dd = *(const float2*)(hid_in + off1 + col);
            float hgx = sk * c[nt][2] + omsk * hh.x;
            float hgy = sk * c[nt][3] + omsk * hh.y;
            float cnx = hgx + cc.x, cny = hgy + cc.y;
            *(float2*)(cn_o + off1 + col) = make_float2(cnx, cny);
            *(float2*)(hid_o + off1 + col) = make_float2(dd.x + tanhf(cnx), dd.y + tanhf(cny));
            pri1 += hgx * swpri[col] + hgy * swpri[col + 1];
        }
    }
    if (l == LL - 1) {
        pri0 += __shfl_xor_sync(0xffffffffu, pri0, 1);
        pri0 += __shfl_xor_sync(0xffffffffu, pri0, 2);
        pri1 += __shfl_xor_sync(0xffffffffu, pri1, 1);
        pri1 += __shfl_xor_sync(0xffffffffu, pri1, 2);
        if ((lane & 3) == 0) {
            if (r0 < cnt) out_pri[nidx[r0]] = 1.0f / (1.0f + __expf(-pri0));
            if (r1 < cnt) out_pri[nidx[r1]] = 1.0f / (1.0f + __expf(-pri1));
        }
    }
}

// ---------------- launch ----------------
extern "C" void kernel_launch(void* const* d_in, const int* in_sizes, int n_in,
                              void* d_out, int out_size) {
    const float* in_hidden = (const float*)d_in[0];
    const float* in_cn     = (const float*)d_in[1];
    const float* in_x      = (const float*)d_in[2];
    const int*   node_type = (const int*)d_in[3];
    const int*   edge_src  = (const int*)d_in[4];
    const int*   edge_dst  = (const int*)d_in[5];
    const float* W_pos     = (const float*)d_in[6];
    const float* Wk        = (const float*)d_in[7];
    const float* Wq        = (const float*)d_in[8];
    const float* Wv        = (const float*)d_in[9];
    const float* Wa        = (const float*)d_in[10];
    const float* rel_att   = (const float*)d_in[11];
    const float* rel_msg   = (const float*)d_in[12];
    const float* rel_pri   = (const float*)d_in[13];
    const float* skip      = (const float*)d_in[14];
    const float* w_pri     = (const float*)d_in[15];

    float* out = (float*)d_out;
    float* out_hid = out;
    float* out_cn = out + (size_t)NN * HH;
    float* out_pri = out + (size_t)2 * NN * HH;

    cudaFuncSetAttribute(k_proj_mma, cudaFuncAttributeMaxDynamicSharedMemorySize, DSMEM_MMA);
    cudaFuncSetAttribute(k_out_mma, cudaFuncAttributeMaxDynamicSharedMemorySize, DSMEM_MMA);

    int nchunks = (NN + 1023) / 1024;  // 49

    k_count<<<1568, 256>>>(edge_dst, node_type);
    k_scanA<<<nchunks, 1024>>>();
    k_scanC<<<196, 256>>>(nchunks);
    k_scatter<<<1568, 256>>>(node_type, edge_src, edge_dst);
    k_combine<<<dim3(TT, 4, LL), 256>>>(Wk, Wq, Wv, Wa, rel_att, rel_msg, rel_pri);

    int tiles128 = (NN + 127) / 128;
    int nodeblk = (NN + 7) / 8;

    for (int l = 0; l < LL; l++) {
        k_proj_mma<<<dim3(tiles128, TT), 256, DSMEM_MMA>>>(in_hidden, in_x, W_pos, l);
        k_edge<<<nodeblk, 256>>>();
        k_out_mma<<<dim3(tiles128, TT), 256, DSMEM_MMA>>>(skip, in_cn, in_hidden, w_pri,
                                                          out_cn, out_hid, out_pri, l);
    }
}

// round 17
// speedup vs baseline: 1.1239x; 1.0442x over previous
#include <cuda_runtime.h>
#include <cuda_bf16.h>
#include <math.h>

#define NN 50000
#define EE 800000
#define HH 128
#define NHH 8
#define DD 16
#define TT 6
#define LL 2

#define APITCH 136                     // bf16 elems per smem row (272 B: conflict-free ldmatrix)
#define ATILE (128 * APITCH * 2)       // bytes per 128x128 bf16 tile with pitch = 34816
#define DSMEM_MMA (3 * ATILE)          // Ahi, Alo, B(single split buffer) = 104448 B -> 2 CTA/SM

typedef unsigned long long u64;
typedef unsigned int u32;

// ---------------- scratch (device globals; no allocation allowed) ----------------
__device__ float g_h[NN * HH];
__device__ __align__(16) __nv_bfloat16 g_ktb[NN * HH];   // bf16 kt (scores only)
__device__ float g_q[NN * HH];
__device__ __align__(16) __nv_bfloat16 g_vmb[NN * HH];   // bf16 vm (messages)
__device__ float g_trans[NN * HH];
__device__ float g_hid[NN * HH];
__device__ float g_cn[NN * HH];
// bf16 split weights per (l,t,mat 0..3): [split2][n128][k128] = 32768 bf16 (65536 B)
__device__ __align__(16) __nv_bfloat16 g_wb[(size_t)LL * TT * 4 * 32768];
__device__ int g_tcnt[TT];
__device__ int g_toff[TT + 1];
__device__ int g_tcur[TT];
__device__ int g_tnodes[NN];
__device__ int g_dcnt[NN];
__device__ int g_doff[NN + 1];
__device__ int g_dcur[NN];
__device__ int g_csrc[EE];
__device__ int g_bsum[64];

// ---------------- helpers ----------------
__device__ __forceinline__ float geluf(float x) {
    float x3 = x * x * x;
    return 0.5f * x * (1.0f + tanhf(0.7978845608028654f * (x + 0.044715f * x3)));
}
__device__ __forceinline__ u32 smem_u32(const void* p) {
    u32 a;
    asm("{ .reg .u64 t; cvta.to.shared.u64 t, %1; cvt.u32.u64 %0, t; }" : "=r"(a) : "l"(p));
    return a;
}
__device__ __forceinline__ void ldsm4(u32* r, u32 addr) {
    asm volatile("ldmatrix.sync.aligned.m8n8.x4.shared.b16 {%0,%1,%2,%3}, [%4];"
                 : "=r"(r[0]), "=r"(r[1]), "=r"(r[2]), "=r"(r[3]) : "r"(addr));
}
__device__ __forceinline__ void ldsm2(u32& r0, u32& r1, u32 addr) {
    asm volatile("ldmatrix.sync.aligned.m8n8.x2.shared.b16 {%0,%1}, [%2];"
                 : "=r"(r0), "=r"(r1) : "r"(addr));
}
__device__ __forceinline__ void mma16816(float* c, const u32* a, u32 b0, u32 b1) {
    asm volatile(
        "mma.sync.aligned.m16n8k16.row.col.f32.bf16.bf16.f32 "
        "{%0,%1,%2,%3}, {%4,%5,%6,%7}, {%8,%9}, {%0,%1,%2,%3};"
        : "+f"(c[0]), "+f"(c[1]), "+f"(c[2]), "+f"(c[3])
        : "r"(a[0]), "r"(a[1]), "r"(a[2]), "r"(a[3]), "r"(b0), "r"(b1));
}
// split fp32x4 -> packed bf16 hi/lo u64s
__device__ __forceinline__ void split4(float4 hv, u64& hp, u64& lp) {
    __nv_bfloat16 h0 = __float2bfloat16(hv.x), h1 = __float2bfloat16(hv.y),
                  h2 = __float2bfloat16(hv.z), h3 = __float2bfloat16(hv.w);
    __nv_bfloat16 l0 = __float2bfloat16(hv.x - __bfloat162float(h0));
    __nv_bfloat16 l1 = __float2bfloat16(hv.y - __bfloat162float(h1));
    __nv_bfloat16 l2 = __float2bfloat16(hv.z - __bfloat162float(h2));
    __nv_bfloat16 l3 = __float2bfloat16(hv.w - __bfloat162float(h3));
    hp = ((u64)((((u32)__bfloat16_as_ushort(h3)) << 16) | __bfloat16_as_ushort(h2)) << 32)
         | ((((u32)__bfloat16_as_ushort(h1)) << 16) | __bfloat16_as_ushort(h0));
    lp = ((u64)((((u32)__bfloat16_as_ushort(l3)) << 16) | __bfloat16_as_ushort(l2)) << 32)
         | ((((u32)__bfloat16_as_ushort(l1)) << 16) | __bfloat16_as_ushort(l0));
}
// 4 consecutive bf16 -> float4 (one LDG.64)
__device__ __forceinline__ float4 ld_bf4(const __nv_bfloat16* p) {
    uint2 r = *(const uint2*)p;
    float2 f0 = __bfloat1622float2(*reinterpret_cast<const __nv_bfloat162*>(&r.x));
    float2 f1 = __bfloat1622float2(*reinterpret_cast<const __nv_bfloat162*>(&r.y));
    return make_float4(f0.x, f0.y, f1.x, f1.y);
}

// ---------------- setup kernels ----------------
__global__ void k_zero() {
    int i = blockIdx.x * blockDim.x + threadIdx.x;
    int stride = gridDim.x * blockDim.x;
    for (int j = i; j < NN; j += stride) { g_dcnt[j] = 0; g_dcur[j] = 0; }
    if (i < TT) { g_tcnt[i] = 0; g_tcur[i] = 0; }
}

__global__ void k_count(const int* __restrict__ edst, const int* __restrict__ nt) {
    __shared__ int sh[TT];
    int tid = threadIdx.x;
    if (tid < TT) sh[tid] = 0;
    __syncthreads();
    int i = blockIdx.x * blockDim.x + tid;
    int stride = gridDim.x * blockDim.x;
    for (int e = i; e < EE; e += stride) atomicAdd(&g_dcnt[edst[e]], 1);
    for (int n = i; n < NN; n += stride) atomicAdd(&sh[nt[n]], 1);
    __syncthreads();
    if (tid < TT) atomicAdd(&g_tcnt[tid], sh[tid]);
}

__global__ void k_scanA() {
    __shared__ int wsum[32];
    int b = blockIdx.x, tid = threadIdx.x, lane = tid & 31, wid = tid >> 5;
    int i = b * 1024 + tid;
    int v = (i < NN) ? g_dcnt[i] : 0;
    int x = v;
    #pragma unroll
    for (int o = 1; o < 32; o <<= 1) {
        int y = __shfl_up_sync(0xffffffffu, x, o);
        if (lane >= o) x += y;
    }
    if (lane == 31) wsum[wid] = x;
    __syncthreads();
    if (wid == 0) {
        int w = wsum[lane];
        #pragma unroll
        for (int o = 1; o < 32; o <<= 1) {
            int y = __shfl_up_sync(0xffffffffu, w, o);
            if (lane >= o) w += y;
        }
        wsum[lane] = w;
    }
    __syncthreads();
    int incl = x + (wid > 0 ? wsum[wid - 1] : 0);
    if (i < NN) g_doff[i] = incl - v;
    if (tid == 1023) g_bsum[b] = incl;
}

// scanC: per-block redundant 64-wide scan of chunk totals; adds base; block 0
// also writes doff[NN] and the type offsets (k_scanB eliminated).
__global__ void k_scanC(int nchunks) {
    __shared__ int schunk[64];
    __shared__ int wtot[2];
    int tid = threadIdx.x;
    int lane = tid & 31;
    if (tid < 64) {
        int v = (tid < nchunks) ? g_bsum[tid] : 0;
        int x = v;
        #pragma unroll
        for (int o = 1; o < 32; o <<= 1) {
            int y = __shfl_up_sync(0xffffffffu, x, o);
            if (lane >= o) x += y;
        }
        if (lane == 31) wtot[tid >> 5] = x;
        schunk[tid] = x - v;   // exclusive within warp
    }
    __syncthreads();
    if (tid >= 32 && tid < 64) schunk[tid] += wtot[0];
    __syncthreads();
    int i = blockIdx.x * blockDim.x + tid;
    if (i < NN) g_doff[i] += schunk[i >> 10];
    if (blockIdx.x == 0 && tid == 0) {
        g_doff[NN] = wtot[0] + wtot[1];
        int r = 0;
        for (int t = 0; t < TT; t++) { g_toff[t] = r; r += g_tcnt[t]; }
        g_toff[TT] = r;
    }
}

__global__ void k_scatter(const int* __restrict__ nt, const int* __restrict__ esrc,
                          const int* __restrict__ edst) {
    int i = blockIdx.x * blockDim.x + threadIdx.x;
    int stride = gridDim.x * blockDim.x;
    for (int n = i; n < NN; n += stride) {
        int t = nt[n];
        int p = atomicAdd(&g_tcur[t], 1);
        g_tnodes[g_toff[t] + p] = n;
    }
    for (int e = i; e < EE; e += stride) {
        int d = edst[e];
        int p = atomicAdd(&g_dcur[d], 1);
        g_csrc[g_doff[d] + p] = esrc[e];
    }
}

// ---------------- weight prep: fold rel matrices, split to bf16 hi/lo ----------------
// mat 0: Wk*rel_att*(rel_pri/4), mat 1: Wq, mat 2: Wv*rel_msg, mat 3: Wa.
__global__ void k_combine(const float* __restrict__ Wk, const float* __restrict__ Wq,
                          const float* __restrict__ Wv, const float* __restrict__ Wa,
                          const float* __restrict__ rel_att, const float* __restrict__ rel_msg,
                          const float* __restrict__ rel_pri) {
    int t = blockIdx.x, mat = blockIdx.y, l = blockIdx.z;
    __shared__ float sA[NHH * DD * DD];
    __shared__ float sScl[NHH];
    const float* W = (mat == 0 ? Wk : (mat == 1 ? Wq : (mat == 2 ? Wv : Wa)))
                     + (size_t)(l * TT + t) * HH * HH;
    const float* A = (mat == 0 ? rel_att : rel_msg) + (size_t)l * NHH * DD * DD;
    __nv_bfloat16* out = g_wb + (((size_t)l * TT + t) * 4 + mat) * 32768;
    bool fold = (mat == 0 || mat == 2);
    if (fold) {
        for (int idx = threadIdx.x; idx < NHH * DD * DD; idx += blockDim.x) sA[idx] = A[idx];
        if (threadIdx.x < NHH)
            sScl[threadIdx.x] = (mat == 0) ? rel_pri[l * NHH + threadIdx.x] * 0.25f : 1.0f;
    }
    __syncthreads();
    for (int idx = threadIdx.x; idx < HH * HH; idx += blockDim.x) {
        int i = idx >> 7, c = idx & 127;
        float v;
        if (!fold) {
            v = W[i * HH + c];
        } else {
            int h = c >> 4, f = c & 15;
            float s = 0.0f;
            #pragma unroll
            for (int d = 0; d < DD; d++)
                s += W[i * HH + h * DD + d] * sA[h * DD * DD + d * DD + f];
            v = s * sScl[h];
        }
        __nv_bfloat16 hi = __float2bfloat16(v);
        __nv_bfloat16 lo = __float2bfloat16(v - __bfloat162float(hi));
        out[c * 128 + i] = hi;
        out[16384 + c * 128 + i] = lo;
    }
}

// ---------------- mma.sync projection kernel ----------------
// kt/vm stored bf16 (halves k_edge gather bytes); q stays fp32.
__global__ void __launch_bounds__(256, 2)
k_proj_mma(const float* __restrict__ ext_hidden, const float* __restrict__ xn,
           const float* __restrict__ Wpos, int l) {
    int t = blockIdx.y;
    int beg = g_toff[t], end = g_toff[t + 1];
    int base = beg + (int)blockIdx.x * 128;
    if (base >= end) return;
    int cnt = min(128, end - base);

    extern __shared__ __align__(16) char dyns[];
    __shared__ int nidx[128];
    __shared__ float sxn0[128], sxn1[128];

    int tid = threadIdx.x;
    int wid = tid >> 5, lane = tid & 31;

    u32 sbase = smem_u32(dyns);
    u32 Ahi = sbase, Alo = sbase + ATILE, Bb = sbase + 2 * ATILE;

    if (tid < 128) {
        int slot = (tid < cnt) ? tid : 0;
        int n = g_tnodes[base + slot];
        nidx[tid] = n;
        sxn0[tid] = (tid < cnt) ? xn[2 * n] : 0.f;
        sxn1[tid] = (tid < cnt) ? xn[2 * n + 1] : 0.f;
    }
    __syncthreads();

    const float* hin = (l == 0) ? ext_hidden : g_hid;
    float4 wpA = ((const float4*)(Wpos + l * 2 * HH))[lane];
    float4 wpB = ((const float4*)(Wpos + l * 2 * HH + HH))[lane];
    #pragma unroll 4
    for (int r = wid; r < 128; r += 8) {
        float4 hv = make_float4(0.f, 0.f, 0.f, 0.f);
        if (r < cnt) {
            size_t rowoff = (size_t)nidx[r] * HH;
            hv = *((const float4*)(hin + rowoff) + lane);
            float x0 = sxn0[r], x1 = sxn1[r];
            hv.x += x0 * wpA.x + x1 * wpB.x;
            hv.y += x0 * wpA.y + x1 * wpB.y;
            hv.z += x0 * wpA.z + x1 * wpB.z;
            hv.w += x0 * wpA.w + x1 * wpB.w;
            *((float4*)(g_h + rowoff) + lane) = hv;
        }
        u64 hp, lp;
        split4(hv, hp, lp);
        u32 off = (u32)r * (APITCH * 2) + (u32)lane * 8;
        *(u64*)(dyns + off) = hp;
        *(u64*)(dyns + ATILE + off) = lp;
    }

    const u64* wb64 = (const u64*)g_wb;
    int m0 = wid * 16;
    u32 aro = (u32)((m0 + (lane & 15)) * APITCH + (lane >> 4) * 8) * 2;
    u32 bro = (u32)(((lane & 7)) * APITCH + ((lane >> 3) & 1) * 8) * 2;
    int r0 = m0 + (lane >> 2), r1 = r0 + 8;

    for (int mat = 0; mat < 3; mat++) {
        float c[16][4];
        #pragma unroll
        for (int nt = 0; nt < 16; nt++) {
            c[nt][0] = 0.f; c[nt][1] = 0.f; c[nt][2] = 0.f; c[nt][3] = 0.f;
        }
        size_t wbase = (((size_t)l * TT + t) * 4 + mat) * 8192;
        #pragma unroll
        for (int s = 0; s < 2; s++) {
            __syncthreads();
            #pragma unroll 4
            for (int j = tid; j < 4096; j += 256) {
                u64 v = wb64[wbase + s * 4096 + j];
                int n = j >> 5, k4 = j & 31;
                *(u64*)(dyns + 2 * ATILE + n * (APITCH * 2) + k4 * 8) = v;
            }
            __syncthreads();
            #pragma unroll
            for (int ks = 0; ks < 8; ks++) {
                u32 a0[4], a1[4];
                ldsm4(a0, Ahi + aro + ks * 32);
                if (s == 0) ldsm4(a1, Alo + aro + ks * 32);
                #pragma unroll
                for (int nt = 0; nt < 16; nt++) {
                    u32 b0, b1;
                    ldsm2(b0, b1, Bb + bro + (u32)nt * 8 * (APITCH * 2) + ks * 32);
                    mma16816(c[nt], a0, b0, b1);
                    if (s == 0) mma16816(c[nt], a1, b0, b1);
                }
            }
        }
        #pragma unroll
        for (int nt = 0; nt < 16; nt++) {
            int col = nt * 8 + (lane & 3) * 2;
            if (mat == 1) {
                if (r0 < cnt)
                    *(float2*)(g_q + (size_t)nidx[r0] * HH + col) = make_float2(c[nt][0], c[nt][1]);
                if (r1 < cnt)
                    *(float2*)(g_q + (size_t)nidx[r1] * HH + col) = make_float2(c[nt][2], c[nt][3]);
            } else {
                __nv_bfloat16* dstb = (mat == 0) ? g_ktb : g_vmb;
                if (r0 < cnt)
                    *(__nv_bfloat162*)(dstb + (size_t)nidx[r0] * HH + col) =
                        __floats2bfloat162_rn(c[nt][0], c[nt][1]);
                if (r1 < cnt)
                    *(__nv_bfloat162*)(dstb + (size_t)nidx[r1] * HH + col) =
                        __floats2bfloat162_rn(c[nt][2], c[nt][3]);
            }
        }
    }
}

// ---------------- edge kernel: bf16 gathers, max-free anchored softmax ----------------
__global__ void k_edge() {
    int warp = threadIdx.x >> 5, lane = threadIdx.x & 31;
    int n = blockIdx.x * 8 + warp;
    if (n >= NN) return;
    int beg = g_doff[n], end = g_doff[n + 1];
    float* outp = g_trans + (size_t)n * HH + lane * 4;
    if (beg == end) {
        *(float4*)outp = make_float4(0.f, 0.f, 0.f, 0.f);
        return;
    }
    float4 q4 = *(const float4*)(g_q + (size_t)n * HH + lane * 4);

    int src0 = g_csrc[beg];
    float4 k0 = ld_bf4(g_ktb + (size_t)src0 * HH + lane * 4);
    float4 v0 = ld_bf4(g_vmb + (size_t)src0 * HH + lane * 4);
    float C = k0.x * q4.x + k0.y * q4.y + k0.z * q4.z + k0.w * q4.w;
    C += __shfl_xor_sync(0xffffffffu, C, 1);
    C += __shfl_xor_sync(0xffffffffu, C, 2);

    float den0 = 1.0f, den1 = 0.0f;
    float ax0 = v0.x, ay0 = v0.y, az0 = v0.z, aw0 = v0.w;
    float ax1 = 0.f, ay1 = 0.f, az1 = 0.f, aw1 = 0.f;

    for (int b = beg + 1; b < end; b += 32) {
        int nchunk = min(32, end - b);
        int srcs = (b + lane < end) ? g_csrc[b + lane] : 0;
        int j = 0;
        for (; j + 2 <= nchunk; j += 2) {
            int sA = __shfl_sync(0xffffffffu, srcs, j);
            int sB = __shfl_sync(0xffffffffu, srcs, j + 1);
            float4 kA = ld_bf4(g_ktb + (size_t)sA * HH + lane * 4);
            float4 kB = ld_bf4(g_ktb + (size_t)sB * HH + lane * 4);
            float4 vA = ld_bf4(g_vmb + (size_t)sA * HH + lane * 4);
            float4 vB = ld_bf4(g_vmb + (size_t)sB * HH + lane * 4);
            float sa = kA.x * q4.x + kA.y * q4.y + kA.z * q4.z + kA.w * q4.w;
            float sb = kB.x * q4.x + kB.y * q4.y + kB.z * q4.z + kB.w * q4.w;
            sa += __shfl_xor_sync(0xffffffffu, sa, 1);
            sb += __shfl_xor_sync(0xffffffffu, sb, 1);
            sa += __shfl_xor_sync(0xffffffffu, sa, 2);
            sb += __shfl_xor_sync(0xffffffffu, sb, 2);
            float pa = __expf(sa - C);
            float pb = __expf(sb - C);
            den0 += pa;             den1 += pb;
            ax0 += pa * vA.x;       ax1 += pb * vB.x;
            ay0 += pa * vA.y;       ay1 += pb * vB.y;
            az0 += pa * vA.z;       az1 += pb * vB.z;
            aw0 += pa * vA.w;       aw1 += pb * vB.w;
        }
        if (j < nchunk) {
            int sA = __shfl_sync(0xffffffffu, srcs, j);
            float4 kA = ld_bf4(g_ktb + (size_t)sA * HH + lane * 4);
            float4 vA = ld_bf4(g_vmb + (size_t)sA * HH + lane * 4);
            float sa = kA.x * q4.x + kA.y * q4.y + kA.z * q4.z + kA.w * q4.w;
            sa += __shfl_xor_sync(0xffffffffu, sa, 1);
            sa += __shfl_xor_sync(0xffffffffu, sa, 2);
            float pa = __expf(sa - C);
            den0 += pa;
            ax0 += pa * vA.x; ay0 += pa * vA.y;
            az0 += pa * vA.z; aw0 += pa * vA.w;
        }
    }
    float inv = 1.0f / (den0 + den1 + 1e-16f);
    float4 o;
    o.x = geluf((ax0 + ax1) * inv);
    o.y = geluf((ay0 + ay1) * inv);
    o.z = geluf((az0 + az1) * inv);
    o.w = geluf((aw0 + aw1) * inv);
    *(float4*)outp = o;
}

// ---------------- mma.sync output kernel: out = trans @ Wa[t] + fused epilogue ----------------
__global__ void __launch_bounds__(256, 2)
k_out_mma(const float* __restrict__ skip,
          const float* __restrict__ ext_cn, const float* __restrict__ ext_hidden,
          const float* __restrict__ w_pri,
          float* __restrict__ out_cn, float* __restrict__ out_hid,
          float* __restrict__ out_pri, int l) {
    int t = blockIdx.y;
    int beg = g_toff[t], end = g_toff[t + 1];
    int base = beg + (int)blockIdx.x * 128;
    if (base >= end) return;
    int cnt = min(128, end - base);

    extern __shared__ __align__(16) char dyns[];
    __shared__ int nidx[128];
    __shared__ float ssk;
    __shared__ float swpri[128];

    int tid = threadIdx.x;
    int wid = tid >> 5, lane = tid & 31;

    u32 sbase = smem_u32(dyns);
    u32 Ahi = sbase, Alo = sbase + ATILE, Bb = sbase + 2 * ATILE;

    if (tid < 128) {
        nidx[tid] = g_tnodes[base + ((tid < cnt) ? tid : 0)];
        swpri[tid] = (l == LL - 1) ? w_pri[l * HH + tid] : 0.f;
    }
    if (tid == 0) ssk = 1.0f / (1.0f + __expf(-skip[l * TT + t]));
    __syncthreads();

    #pragma unroll 4
    for (int r = wid; r < 128; r += 8) {
        float4 hv = make_float4(0.f, 0.f, 0.f, 0.f);
        if (r < cnt)
            hv = *((const float4*)(g_trans + (size_t)nidx[r] * HH) + lane);
        u64 hp, lp;
        split4(hv, hp, lp);
        u32 off = (u32)r * (APITCH * 2) + (u32)lane * 8;
        *(u64*)(dyns + off) = hp;
        *(u64*)(dyns + ATILE + off) = lp;
    }

    const u64* wb64 = (const u64*)g_wb;
    int m0 = wid * 16;
    u32 aro = (u32)((m0 + (lane & 15)) * APITCH + (lane >> 4) * 8) * 2;
    u32 bro = (u32)(((lane & 7)) * APITCH + ((lane >> 3) & 1) * 8) * 2;
    int r0 = m0 + (lane >> 2), r1 = r0 + 8;

    float c[16][4];
    #pragma unroll
    for (int nt = 0; nt < 16; nt++) {
        c[nt][0] = 0.f; c[nt][1] = 0.f; c[nt][2] = 0.f; c[nt][3] = 0.f;
    }
    size_t wbase = (((size_t)l * TT + t) * 4 + 3) * 8192;   // mat 3 = Wa
    #pragma unroll
    for (int s = 0; s < 2; s++) {
        __syncthreads();
        #pragma unroll 4
        for (int j = tid; j < 4096; j += 256) {
            u64 v = wb64[wbase + s * 4096 + j];
            int n = j >> 5, k4 = j & 31;
            *(u64*)(dyns + 2 * ATILE + n * (APITCH * 2) + k4 * 8) = v;
        }
        __syncthreads();
        #pragma unroll
        for (int ks = 0; ks < 8; ks++) {
            u32 a0[4], a1[4];
            ldsm4(a0, Ahi + aro + ks * 32);
            if (s == 0) ldsm4(a1, Alo + aro + ks * 32);
            #pragma unroll
            for (int nt = 0; nt < 16; nt++) {
                u32 b0, b1;
                ldsm2(b0, b1, Bb + bro + (u32)nt * 8 * (APITCH * 2) + ks * 32);
                mma16816(c[nt], a0, b0, b1);
                if (s == 0) mma16816(c[nt], a1, b0, b1);
            }
        }
    }

    const float* cn_in = (l == 0) ? ext_cn : g_cn;
    const float* hid_in = (l == 0) ? ext_hidden : g_hid;
    float* cn_o = (l == LL - 1) ? out_cn : g_cn;
    float* hid_o = (l == LL - 1) ? out_hid : g_hid;
    float sk = ssk, omsk = 1.0f - ssk;
    float pri0 = 0.f, pri1 = 0.f;
    size_t off0 = (size_t)nidx[r0 < cnt ? r0 : 0] * HH;
    size_t off1 = (size_t)nidx[r1 < cnt ? r1 : 0] * HH;
    #pragma unroll
    for (int nt = 0; nt < 16; nt++) {
        int col = nt * 8 + (lane & 3) * 2;
        if (r0 < cnt) {
            float2 hh = *(const float2*)(g_h + off0 + col);
            float2 cc = *(const float2*)(cn_in + off0 + col);
            float2 dd = *(const float2*)(hid_in + off0 + col);
            float hgx = sk * c[nt][0] + omsk * hh.x;
            float hgy = sk * c[nt][1] + omsk * hh.y;
            float cnx = hgx + cc.x, cny = hgy + cc.y;
            *(float2*)(cn_o + off0 + col) = make_float2(cnx, cny);
            *(float2*)(hid_o + off0 + col) = make_float2(dd.x + tanhf(cnx), dd.y + tanhf(cny));
            pri0 += hgx * swpri[col] + hgy * swpri[col + 1];
        }
        if (r1 < cnt) {
            float2 hh = *(const float2*)(g_h + off1 + col);
            float2 cc = *(const float2*)(cn_in + off1 + col);
            float2 dd = *(const float2*)(hid_in + off1 + col);
            float hgx = sk * c[nt][2] + omsk * hh.x;
            float hgy = sk * c[nt][3] + omsk * hh.y;
            float cnx = hgx + cc.x, cny = hgy + cc.y;
            *(float2*)(cn_o + off1 + col) = make_float2(cnx, cny);
            *(float2*)(hid_o + off1 + col) = make_float2(dd.x + tanhf(cnx), dd.y + tanhf(cny));
            pri1 += hgx * swpri[col] + hgy * swpri[col + 1];
        }
    }
    if (l == LL - 1) {
        pri0 += __shfl_xor_sync(0xffffffffu, pri0, 1);
        pri0 += __shfl_xor_sync(0xffffffffu, pri0, 2);
        pri1 += __shfl_xor_sync(0xffffffffu, pri1, 1);
        pri1 += __shfl_xor_sync(0xffffffffu, pri1, 2);
        if ((lane & 3) == 0) {
            if (r0 < cnt) out_pri[nidx[r0]] = 1.0f / (1.0f + __expf(-pri0));
            if (r1 < cnt) out_pri[nidx[r1]] = 1.0f / (1.0f + __expf(-pri1));
        }
    }
}

// ---------------- launch ----------------
extern "C" void kernel_launch(void* const* d_in, const int* in_sizes, int n_in,
                              void* d_out, int out_size) {
    const float* in_hidden = (const float*)d_in[0];
    const float* in_cn     = (const float*)d_in[1];
    const float* in_x      = (const float*)d_in[2];
    const int*   node_type = (const int*)d_in[3];
    const int*   edge_src  = (const int*)d_in[4];
    const int*   edge_dst  = (const int*)d_in[5];
    const float* W_pos     = (const float*)d_in[6];
    const float* Wk        = (const float*)d_in[7];
    const float* Wq        = (const float*)d_in[8];
    const float* Wv        = (const float*)d_in[9];
    const float* Wa        = (const float*)d_in[10];
    const float* rel_att   = (const float*)d_in[11];
    const float* rel_msg   = (const float*)d_in[12];
    const float* rel_pri   = (const float*)d_in[13];
    const float* skip      = (const float*)d_in[14];
    const float* w_pri     = (const float*)d_in[15];

    float* out = (float*)d_out;
    float* out_hid = out;
    float* out_cn = out + (size_t)NN * HH;
    float* out_pri = out + (size_t)2 * NN * HH;

    cudaFuncSetAttribute(k_proj_mma, cudaFuncAttributeMaxDynamicSharedMemorySize, DSMEM_MMA);
    cudaFuncSetAttribute(k_out_mma, cudaFuncAttributeMaxDynamicSharedMemorySize, DSMEM_MMA);

    int nchunks = (NN + 1023) / 1024;  // 49

    k_zero<<<196, 256>>>();
    k_count<<<1568, 256>>>(edge_dst, node_type);
    k_scanA<<<nchunks, 1024>>>();
    k_scanC<<<196, 256>>>(nchunks);
    k_scatter<<<1568, 256>>>(node_type, edge_src, edge_dst);
    k_combine<<<dim3(TT, 4, LL), 256>>>(Wk, Wq, Wv, Wa, rel_att, rel_msg, rel_pri);

    int tiles128 = (NN + 127) / 128;
    int nodeblk = (NN + 7) / 8;

    for (int l = 0; l < LL; l++) {
        k_proj_mma<<<dim3(tiles128, TT), 256, DSMEM_MMA>>>(in_hidden, in_x, W_pos, l);
        k_edge<<<nodeblk, 256>>>();
        k_out_mma<<<dim3(tiles128, TT), 256, DSMEM_MMA>>>(skip, in_cn, in_hidden, w_pri,
                                                          out_cn, out_hid, out_pri, l);
    }
}